// round 14
// baseline (speedup 1.0000x reference)
#include <cuda_runtime.h>
#include <cuda_bf16.h>
#include <math.h>

// ============================================================================
// BatchNormSPDMean R14: odd-even register Jacobi with ONE barrier per
// round-pair (left-pair params computed locally, bitwise-identical to the
// neighbor's) + sweep schedule 6/6/7.
// ============================================================================

#define NN 4096
#define LD 65        // single-matrix kernels row stride
#define BLD 66       // batch row-major stride
#define CST 68       // batch col-major column stride
#define BUFB 4352
#define NSWEEP_S 10
#define TPB 256
#define BUF 4160
#define FULLM 0xffffffffu

typedef unsigned long long ull;

__device__ float g_M [NN];
__device__ float g_Ms[NN];
__device__ float g_Mi[NN];
__device__ float g_T [NN];
__device__ float g_W [NN];

// ---- f32x2 helpers ----
__device__ __forceinline__ ull pk2(float lo, float hi) {
    ull r; asm("mov.b64 %0,{%1,%2};" : "=l"(r) : "f"(lo), "f"(hi)); return r;
}
__device__ __forceinline__ float2 upk2(ull v) {
    float2 r; asm("mov.b64 {%0,%1},%2;" : "=f"(r.x), "=f"(r.y) : "l"(v)); return r;
}
__device__ __forceinline__ ull fma2(ull a, ull b, ull c) {
    ull r; asm("fma.rn.f32x2 %0,%1,%2,%3;" : "=l"(r) : "l"(a), "l"(b), "l"(c)); return r;
}
__device__ __forceinline__ ull mul2(ull a, ull b) {
    ull r; asm("mul.rn.f32x2 %0,%1,%2;" : "=l"(r) : "l"(a), "l"(b)); return r;
}
__device__ __forceinline__ float hadd2(ull v) { float2 f = upk2(v); return f.x + f.y; }
__device__ __forceinline__ float d4(float4 a, float4 b) {
    return fmaf(a.x, b.x, fmaf(a.y, b.y, fmaf(a.z, b.z, a.w * b.w)));
}
// collective: all 32 lanes must execute (full-mask shfl)
__device__ __forceinline__ void dots2(const ull* u, const ull* v, float& dd, float& apq) {
    ull U = mul2(u[0], u[0]), V = mul2(v[0], v[0]), P = mul2(u[0], v[0]);
#pragma unroll
    for (int i = 1; i < 4; i++) {
        U = fma2(u[i], u[i], U); V = fma2(v[i], v[i], V); P = fma2(u[i], v[i], P);
    }
    float d = hadd2(V) - hadd2(U);
    float p = hadd2(P);
#pragma unroll
    for (int k = 1; k < 8; k <<= 1) {
        d += __shfl_xor_sync(FULLM, d, k);
        p += __shfl_xor_sync(FULLM, p, k);
    }
    dd = d; apq = p;
}
__device__ __forceinline__ void rot_params2(float dd, float apq, float& c, float& s) {
    if (fabsf(apq) > 1e-34f) {
        float tau = __fdividef(dd, 2.f * apq);
        float tt  = copysignf(1.f, tau) / (fabsf(tau) + sqrtf(1.f + tau * tau));
        c = rsqrtf(1.f + tt * tt);
        s = tt * c;
    } else { c = 1.f; s = 0.f; }
}
__device__ __forceinline__ void get_pair(int r, int k, int& p, int& q) {
    int a = (k == 0) ? 0 : 1 + (k - 1 + r) % 63;
    int b = 1 + (62 - k + r) % 63;
    p = a < b ? a : b;
    q = a < b ? b : a;
}

// ---- single-matrix helpers ----
__device__ __forceinline__ void load_g2s(const float* __restrict__ g, float* S) {
    for (int idx = threadIdx.x; idx < NN; idx += TPB)
        S[(idx >> 6) * LD + (idx & 63)] = g[idx];
}
__device__ __forceinline__ void store_s2g(const float* S, float* __restrict__ g) {
    for (int idx = threadIdx.x; idx < NN; idx += TPB)
        g[idx] = S[(idx >> 6) * LD + (idx & 63)];
}
__device__ __forceinline__ void sym_s(float* A) {
    for (int idx = threadIdx.x; idx < NN; idx += TPB) {
        int i = idx >> 6, j = idx & 63;
        if (i < j) {
            float v = 0.5f * (A[i * LD + j] + A[j * LD + i]);
            A[i * LD + j] = v; A[j * LD + i] = v;
        }
    }
}
__device__ __forceinline__ void smm(const float* A, const float* B, float* C) {
    int j = threadIdx.x & 63, ib = (threadIdx.x >> 6) << 4;
    float acc[16];
#pragma unroll
    for (int i = 0; i < 16; i++) acc[i] = 0.f;
    for (int k = 0; k < 64; k++) {
        float bv = B[k * LD + j];
#pragma unroll
        for (int i = 0; i < 16; i++) acc[i] = fmaf(A[(ib + i) * LD + k], bv, acc[i]);
    }
#pragma unroll
    for (int i = 0; i < 16; i++) C[(ib + i) * LD + j] = acc[i];
}
__device__ __forceinline__ void smm_bt(const float* A, const float* B, float* C) {
    int j = threadIdx.x & 63, ib = (threadIdx.x >> 6) << 4;
    float acc[16];
#pragma unroll
    for (int i = 0; i < 16; i++) acc[i] = 0.f;
    for (int k = 0; k < 64; k++) {
        float bv = B[j * LD + k];
#pragma unroll
        for (int i = 0; i < 16; i++) acc[i] = fmaf(A[(ib + i) * LD + k], bv, acc[i]);
    }
#pragma unroll
    for (int i = 0; i < 16; i++) C[(ib + i) * LD + j] = acc[i];
}
__device__ __forceinline__ void smm_glob(const float* A, const float* B, float* __restrict__ g) {
    int j = threadIdx.x & 63, ib = (threadIdx.x >> 6) << 4;
    float acc[16];
#pragma unroll
    for (int i = 0; i < 16; i++) acc[i] = 0.f;
    for (int k = 0; k < 64; k++) {
        float bv = B[k * LD + j];
#pragma unroll
        for (int i = 0; i < 16; i++) acc[i] = fmaf(A[(ib + i) * LD + k], bv, acc[i]);
    }
#pragma unroll
    for (int i = 0; i < 16; i++) g[(ib + i) * 64 + j] = acc[i];
}
__device__ __forceinline__ void scalecols(const float* V, const float* w, float* O) {
    for (int idx = threadIdx.x; idx < NN; idx += TPB) {
        int i = idx >> 6, k = idx & 63;
        O[i * LD + k] = V[i * LD + k] * w[k];
    }
}

__device__ void jacobi2s(float* A, float* V, int nsweeps) {
    int t = threadIdx.x;
    __shared__ float cs[32], sn[32];
    __shared__ uchar2 tab2[63 * 32];
    for (int idx = t; idx < 63 * 32; idx += TPB) {
        int r = idx >> 5, k = idx & 31, p, q;
        get_pair(r, k, p, q);
        tab2[idx] = make_uchar2((unsigned char)p, (unsigned char)q);
    }
    for (int idx = t; idx < NN; idx += TPB) {
        int i = idx >> 6, j = idx & 63;
        V[i * LD + j] = (i == j) ? 1.f : 0.f;
    }
    __syncthreads();
    for (int sw = 0; sw < nsweeps; ++sw)
        for (int r = 0; r < 63; ++r) {
            const uchar2* trow = tab2 + (r << 5);
            if (t < 32) {
                uchar2 pq = trow[t];
                int pl = pq.x * LD, ql = pq.y * LD;
                float app = A[pl + pq.x], aqq = A[ql + pq.y], apq = A[pl + pq.y];
                float c, s;
                if (fabsf(apq) < 1e-30f) { c = 1.f; s = 0.f; }
                else {
                    float tau = (aqq - app) / (2.f * apq);
                    float tt  = copysignf(1.f, tau) / (fabsf(tau) + sqrtf(1.f + tau * tau));
                    c = rsqrtf(1.f + tt * tt); s = tt * c;
                }
                cs[t] = c; sn[t] = s;
            }
            __syncthreads();
#pragma unroll
            for (int m = 0; m < 2048 / TPB; m++) {
                int w = t + m * TPB, k = w >> 6, j = w & 63;
                uchar2 pq = trow[k];
                int pl = pq.x * LD + j, ql = pq.y * LD + j;
                float c = cs[k], s = sn[k];
                float ap = A[pl], aq = A[ql];
                A[pl] = c * ap - s * aq;
                A[ql] = fmaf(s, ap, c * aq);
            }
            __syncthreads();
#pragma unroll
            for (int m = 0; m < 2048 / TPB; m++) {
                int w = t + m * TPB, k = w >> 6, i = w & 63;
                uchar2 pq = trow[k];
                int il = i * LD, pl = il + pq.x, ql = il + pq.y;
                float c = cs[k], s = sn[k];
                float ap = A[pl], aq = A[ql];
                A[pl] = c * ap - s * aq;
                A[ql] = fmaf(s, ap, c * aq);
                float vp = V[pl], vq = V[ql];
                V[pl] = c * vp - s * vq;
                V[ql] = fmaf(s, vp, c * vq);
            }
            __syncthreads();
        }
}

// ---- batch GEMMs ----
__device__ __forceinline__ void gemm_rr(const float* A, const float* B, float* C) {
    int j = threadIdx.x & 63, ib = (threadIdx.x >> 6) << 4;
    ull acc[16];
#pragma unroll
    for (int i = 0; i < 16; i++) acc[i] = 0ull;
    for (int k = 0; k < 64; k += 2) {
        ull b2 = pk2(B[k * BLD + j], B[(k + 1) * BLD + j]);
#pragma unroll
        for (int i = 0; i < 16; i++)
            acc[i] = fma2(*(const ull*)(A + (ib + i) * BLD + k), b2, acc[i]);
    }
#pragma unroll
    for (int i = 0; i < 16; i++) { float2 f = upk2(acc[i]); C[(ib + i) * BLD + j] = f.x + f.y; }
}
__device__ __forceinline__ void gemm_r2c(const float* A, const float* B, float* C) {
    int j = threadIdx.x & 63, ib = (threadIdx.x >> 6) << 4;
    ull acc[16];
#pragma unroll
    for (int i = 0; i < 16; i++) acc[i] = 0ull;
    for (int k = 0; k < 64; k += 2) {
        ull b2 = pk2(B[k * BLD + j], B[(k + 1) * BLD + j]);
#pragma unroll
        for (int i = 0; i < 16; i++)
            acc[i] = fma2(*(const ull*)(A + (ib + i) * BLD + k), b2, acc[i]);
    }
    float r[16];
#pragma unroll
    for (int i = 0; i < 16; i++) { float2 f = upk2(acc[i]); r[i] = f.x + f.y; }
    float4* dst = (float4*)(C + j * CST + ib);
    dst[0] = make_float4(r[0], r[1], r[2], r[3]);
    dst[1] = make_float4(r[4], r[5], r[6], r[7]);
    dst[2] = make_float4(r[8], r[9], r[10], r[11]);
    dst[3] = make_float4(r[12], r[13], r[14], r[15]);
}

__device__ __forceinline__ void colscale_log(const float* B, float* W) {
    int t = threadIdx.x, col = t >> 2, qc = t & 3;
    const float4* bc = (const float4*)(B + col * CST);
    float4 v0 = bc[qc * 4 + 0], v1 = bc[qc * 4 + 1];
    float4 v2 = bc[qc * 4 + 2], v3 = bc[qc * 4 + 3];
    float pn = d4(v0, v0) + d4(v1, v1) + d4(v2, v2) + d4(v3, v3);
    pn += __shfl_xor_sync(FULLM, pn, 1);
    pn += __shfl_xor_sync(FULLM, pn, 2);
    float n2 = fmaxf(pn, 1e-24f);
    float g = 0.5f * logf(n2) / n2;
    float4* wc = (float4*)(W + col * CST);
    v0.x *= g; v0.y *= g; v0.z *= g; v0.w *= g;
    v1.x *= g; v1.y *= g; v1.z *= g; v1.w *= g;
    v2.x *= g; v2.y *= g; v2.z *= g; v2.w *= g;
    v3.x *= g; v3.y *= g; v3.z *= g; v3.w *= g;
    wc[qc * 4 + 0] = v0; wc[qc * 4 + 1] = v1;
    wc[qc * 4 + 2] = v2; wc[qc * 4 + 3] = v3;
}
__device__ __forceinline__ void logm_atomic(const float* W, const float* B, float scale) {
    int j = threadIdx.x & 63, ib = (threadIdx.x >> 6) << 4;
    float acc[16];
#pragma unroll
    for (int i = 0; i < 16; i++) acc[i] = 0.f;
    for (int k = 0; k < 64; k++) {
        float bj = B[k * CST + j];
        const float4* wr = (const float4*)(W + k * CST + ib);
        float4 w0 = wr[0], w1 = wr[1], w2 = wr[2], w3 = wr[3];
        acc[0]  = fmaf(w0.x, bj, acc[0]);  acc[1]  = fmaf(w0.y, bj, acc[1]);
        acc[2]  = fmaf(w0.z, bj, acc[2]);  acc[3]  = fmaf(w0.w, bj, acc[3]);
        acc[4]  = fmaf(w1.x, bj, acc[4]);  acc[5]  = fmaf(w1.y, bj, acc[5]);
        acc[6]  = fmaf(w1.z, bj, acc[6]);  acc[7]  = fmaf(w1.w, bj, acc[7]);
        acc[8]  = fmaf(w2.x, bj, acc[8]);  acc[9]  = fmaf(w2.y, bj, acc[9]);
        acc[10] = fmaf(w2.z, bj, acc[10]); acc[11] = fmaf(w2.w, bj, acc[11]);
        acc[12] = fmaf(w3.x, bj, acc[12]); acc[13] = fmaf(w3.y, bj, acc[13]);
        acc[14] = fmaf(w3.z, bj, acc[14]); acc[15] = fmaf(w3.w, bj, acc[15]);
    }
#pragma unroll
    for (int i = 0; i < 16; i++) atomicAdd(&g_T[(ib + i) * 64 + j], acc[i] * scale);
}

// ---- kernels ----
__global__ void k_zero(int which) {
    int i = blockIdx.x * blockDim.x + threadIdx.x;
    if (i < NN) { if (which == 0) g_M[i] = 0.f; else g_T[i] = 0.f; }
}
__global__ void k_mean_acc(const float* __restrict__ data, int per_chunk, float inv_nb) {
    int e = blockIdx.x * blockDim.x + threadIdx.x;
    const float* p = data + (size_t)(blockIdx.y) * per_chunk * NN + e;
    float sum = 0.f;
#pragma unroll 8
    for (int i = 0; i < per_chunk; i++) sum += p[(size_t)i * NN];
    atomicAdd(&g_M[e], sum * inv_nb);
}
__global__ void __launch_bounds__(TPB) k_eig_M() {
    extern __shared__ float sm[];
    float* A = sm; float* V = sm + BUF; float* T1 = sm + 2 * BUF; float* T2 = sm + 3 * BUF;
    __shared__ float w1[64], w2[64];
    load_g2s(g_M, A); __syncthreads();
    sym_s(A); __syncthreads();
    jacobi2s(A, V, NSWEEP_S);
    int t = threadIdx.x;
    if (t < 64) {
        float w = fmaxf(A[t * LD + t], 1e-12f);
        w1[t] = sqrtf(w); w2[t] = rsqrtf(w);
    }
    __syncthreads();
    scalecols(V, w1, T1); __syncthreads();
    smm_bt(T1, V, T2);    __syncthreads();
    store_s2g(T2, g_Ms);  __syncthreads();
    scalecols(V, w2, T1); __syncthreads();
    smm_bt(T1, V, T2);    __syncthreads();
    store_s2g(T2, g_Mi);
}

// batch step: C = Mi*D*Mi; register odd-even one-sided Jacobi; T += logm(C)/nb
__global__ void __launch_bounds__(TPB, 4) k_batch_oe(const float* __restrict__ data,
                                                     float inv_nb, int nsweep) {
    extern __shared__ float sm[];
    float* s0 = sm;             // Mi(row) -> xL overlay -> W(col)
    float* s1 = sm + BUFB;      // D(row) -> C(col) -> B(col)
    float* s2 = sm + 2 * BUFB;  // temp(row) -> xR overlay
    int t = threadIdx.x;
    size_t b = blockIdx.x;

    for (int idx = t; idx < NN; idx += TPB)
        s0[(idx >> 6) * BLD + (idx & 63)] = g_Mi[idx];
    const float* D = data + b * NN;
    for (int idx = t; idx < NN; idx += TPB)
        s1[(idx >> 6) * BLD + (idx & 63)] = D[idx];
    __syncthreads();
    gemm_rr(s0, s1, s2);    // s2 = Mi*D (row)
    __syncthreads();
    gemm_r2c(s2, s0, s1);   // s1 = C (col CST)
    __syncthreads();
    for (int idx = t; idx < NN; idx += TPB) {   // symmetrize
        int i = idx >> 6, j = idx & 63;
        if (i < j) {
            float v = 0.5f * (s1[i * CST + j] + s1[j * CST + i]);
            s1[i * CST + j] = v; s1[j * CST + i] = v;
        }
    }
    __syncthreads();

    // ---- load 2 columns per 8-lane group into registers ----
    int lane = t & 31, warp = t >> 5, grp = lane >> 3, sub = lane & 7;
    int G = warp * 4 + grp;
    ull cL[4], cR[4];
    {
        const ulonglong2* pc = (const ulonglong2*)(s1 + (2 * G) * CST);
        ulonglong2 q0 = pc[2 * sub], q1 = pc[2 * sub + 1];
        cL[0] = q0.x; cL[1] = q0.y; cL[2] = q1.x; cL[3] = q1.y;
        const ulonglong2* pd = (const ulonglong2*)(s1 + (2 * G + 1) * CST);
        q0 = pd[2 * sub]; q1 = pd[2 * sub + 1];
        cR[0] = q0.x; cR[1] = q0.y; cR[2] = q1.x; cR[3] = q1.y;
    }
    __syncthreads();   // s0/s2 freed for xbuf overlays

    const bool hasR = (G < 31);
    const bool hasL = (G > 0);
    int pb = 0;
    for (int sw = 0; sw < nsweep; ++sw)
        for (int rr = 0; rr < 32; ++rr) {
            {   // EVEN round: pair (2G, 2G+1), registers only, swap
                float dd, apq;
                dots2(cL, cR, dd, apq);
                float c, s;
                rot_params2(dd, apq, c, s);
                ull c2 = pk2(c, c), s2p = pk2(s, s), ns2 = pk2(-s, -s);
#pragma unroll
                for (int i = 0; i < 4; i++) {
                    ull u = cL[i], v = cR[i];
                    cL[i] = fma2(s2p, u, mul2(c2, v));
                    cR[i] = fma2(ns2, v, mul2(c2, u));
                }
            }
            {   // ODD round: pairs (2G+1, 2G+2) and (2G-1, 2G); ONE barrier.
                // Left-pair params computed locally from (uL, cL) — bitwise
                // identical to the right neighbor's (cR, vR) computation.
                float4* Lb = (float4*)(s0 + ((pb << 5) + G) * 64);
                float4* Rb = (float4*)(s2 + ((pb << 5) + G) * 64);
                Lb[sub]     = *(float4*)&cL[0];
                Lb[sub + 8] = *(float4*)&cL[2];
                Rb[sub]     = *(float4*)&cR[0];
                Rb[sub + 8] = *(float4*)&cR[2];
                __syncthreads();
                ull vR[4] = {0, 0, 0, 0}, uL[4] = {0, 0, 0, 0};
                if (hasR) {
                    const float4* p = (const float4*)(s0 + ((pb << 5) + G + 1) * 64);
                    *(float4*)&vR[0] = p[sub];
                    *(float4*)&vR[2] = p[sub + 8];
                }
                if (hasL) {
                    const float4* p = (const float4*)(s2 + ((pb << 5) + G - 1) * 64);
                    *(float4*)&uL[0] = p[sub];
                    *(float4*)&uL[2] = p[sub + 8];
                }
                // both collectives unconditional (zero neighbors -> identity)
                float ddR, apqR, ddL, apqL;
                dots2(cR, vR, ddR, apqR);
                dots2(uL, cL, ddL, apqL);
                float c, s, cl, sl;
                rot_params2(ddR, apqR, c, s);
                rot_params2(ddL, apqL, cl, sl);
                if (hasR) {
                    ull c2 = pk2(c, c), s2p = pk2(s, s);
#pragma unroll
                    for (int i = 0; i < 4; i++)
                        cR[i] = fma2(s2p, cR[i], mul2(c2, vR[i]));   // v' = s u + c v
                }
                if (hasL) {
                    ull cl2 = pk2(cl, cl), nsl2 = pk2(-sl, -sl);
#pragma unroll
                    for (int i = 0; i < 4; i++)
                        cL[i] = fma2(nsl2, cL[i], mul2(cl2, uL[i])); // u' = c u - s v
                }
                pb ^= 1;
            }
        }

    // store columns back to s1 (col CST), permutation irrelevant
    {
        ulonglong2* pc = (ulonglong2*)(s1 + (2 * G) * CST);
        pc[2 * sub]     = make_ulonglong2(cL[0], cL[1]);
        pc[2 * sub + 1] = make_ulonglong2(cL[2], cL[3]);
        ulonglong2* pd = (ulonglong2*)(s1 + (2 * G + 1) * CST);
        pd[2 * sub]     = make_ulonglong2(cR[0], cR[1]);
        pd[2 * sub + 1] = make_ulonglong2(cR[2], cR[3]);
    }
    __syncthreads();
    colscale_log(s1, s0);
    __syncthreads();
    logm_atomic(s0, s1, inv_nb);
}

__global__ void __launch_bounds__(TPB) k_update_M() {
    extern __shared__ float sm[];
    float* A = sm; float* V = sm + BUF; float* T1 = sm + 2 * BUF; float* T2 = sm + 3 * BUF;
    __shared__ float ew[64];
    load_g2s(g_T, A); __syncthreads();
    sym_s(A); __syncthreads();
    jacobi2s(A, V, NSWEEP_S);
    int t = threadIdx.x;
    if (t < 64) ew[t] = expf(A[t * LD + t]);
    __syncthreads();
    scalecols(V, ew, T1); __syncthreads();
    smm_bt(T1, V, T2);    __syncthreads();
    load_g2s(g_Ms, A);    __syncthreads();
    smm(A, T2, T1);       __syncthreads();
    smm_glob(T1, A, g_M);
}
__global__ void __launch_bounds__(TPB) k_bias(const float* __restrict__ bias) {
    extern __shared__ float sm[];
    float* A = sm; float* V = sm + BUF; float* T1 = sm + 2 * BUF; float* T2 = sm + 3 * BUF;
    __shared__ float ew[64];
    int t = threadIdx.x;
    for (int idx = t; idx < NN; idx += TPB) {
        int i = idx >> 6, j = idx & 63;
        A[i * LD + j] = 0.5f * (bias[i * 64 + j] + bias[j * 64 + i]);
    }
    __syncthreads();
    jacobi2s(A, V, NSWEEP_S);
    if (t < 64) ew[t] = expf(0.5f * A[t * LD + t]);
    __syncthreads();
    scalecols(V, ew, T1); __syncthreads();
    smm_bt(T1, V, T2);    __syncthreads();
    load_g2s(g_Mi, A);    __syncthreads();
    smm_glob(T2, A, g_W);
}
__global__ void __launch_bounds__(TPB, 4) k_final(const float* __restrict__ data,
                                                  float* __restrict__ out) {
    extern __shared__ float sm[];
    float* sW = sm; float* sD = sm + BUFB; float* sT = sm + 2 * BUFB;
    size_t b = blockIdx.x;
    int t = threadIdx.x;
    for (int idx = t; idx < NN; idx += TPB)
        sW[(idx >> 6) * BLD + (idx & 63)] = g_W[idx];
    const float* D = data + b * NN;
    for (int idx = t; idx < NN; idx += TPB)
        sD[(idx >> 6) * BLD + (idx & 63)] = D[idx];
    __syncthreads();
    gemm_rr(sW, sD, sT);
    __syncthreads();
    int j = t & 63, ib = (t >> 6) << 4;
    ull acc[16];
#pragma unroll
    for (int i = 0; i < 16; i++) acc[i] = 0ull;
    for (int k = 0; k < 64; k += 2) {
        ull b2 = *(const ull*)(sW + j * BLD + k);
#pragma unroll
        for (int i = 0; i < 16; i++)
            acc[i] = fma2(*(const ull*)(sT + (ib + i) * BLD + k), b2, acc[i]);
    }
    float* o = out + b * NN;
#pragma unroll
    for (int i = 0; i < 16; i++) { float2 f = upk2(acc[i]); o[(ib + i) * 64 + j] = f.x + f.y; }
}

// ---------------------------------------------------------------------------
extern "C" void kernel_launch(void* const* d_in, const int* in_sizes, int n_in,
                              void* d_out, int out_size) {
    const float* data;
    const float* bias;
    int nb;
    if (in_sizes[0] >= in_sizes[1]) {
        data = (const float*)d_in[0]; bias = (const float*)d_in[1];
        nb = in_sizes[0] / NN;
    } else {
        data = (const float*)d_in[1]; bias = (const float*)d_in[0];
        nb = in_sizes[1] / NN;
    }
    float* out = (float*)d_out;
    float inv_nb = 1.0f / (float)nb;

    size_t smemS = 4 * BUF  * sizeof(float);
    size_t smemB = 3 * BUFB * sizeof(float);
    cudaFuncSetAttribute(k_eig_M,    cudaFuncAttributeMaxDynamicSharedMemorySize, (int)smemS);
    cudaFuncSetAttribute(k_batch_oe, cudaFuncAttributeMaxDynamicSharedMemorySize, (int)smemB);
    cudaFuncSetAttribute(k_update_M, cudaFuncAttributeMaxDynamicSharedMemorySize, (int)smemS);
    cudaFuncSetAttribute(k_bias,     cudaFuncAttributeMaxDynamicSharedMemorySize, (int)smemS);
    cudaFuncSetAttribute(k_final,    cudaFuncAttributeMaxDynamicSharedMemorySize, (int)smemB);

    k_zero<<<16, 256>>>(0);
    {
        int nchunk = 64;
        while (nchunk > 1 && (nb % nchunk) != 0) nchunk >>= 1;
        int per_chunk = nb / nchunk;
        dim3 g(NN / 256, nchunk);
        k_mean_acc<<<g, 256>>>(data, per_chunk, inv_nb);
    }

    // Karcher iterations: sweep schedule 6/6/7 (early residuals are damped)
    const int sweeps[3] = {6, 6, 7};
    for (int it = 0; it < 3; ++it) {
        k_eig_M<<<1, TPB, smemS>>>();
        k_zero<<<16, 256>>>(1);
        k_batch_oe<<<nb, TPB, smemB>>>(data, inv_nb, sweeps[it]);
        k_update_M<<<1, TPB, smemS>>>();
    }

    k_eig_M<<<1, TPB, smemS>>>();
    k_bias<<<1, TPB, smemS>>>(bias);
    k_final<<<nb, TPB, smemB>>>(data, out);
}

// round 15
// speedup vs baseline: 1.1184x; 1.1184x over previous
#include <cuda_runtime.h>
#include <cuda_bf16.h>
#include <math.h>

// ============================================================================
// BatchNormSPDMean R15: R13 Jacobi (param relay, 2 barriers/round-pair —
// measured faster than local dual-dots) + sweep schedule 6/6/7 (validated
// at rel_err 2.9e-4 in R14).
// ============================================================================

#define NN 4096
#define LD 65        // single-matrix kernels row stride
#define BLD 66       // batch row-major stride
#define CST 68       // batch col-major column stride
#define BUFB 4352
#define NSWEEP_S 10
#define TPB 256
#define BUF 4160
#define FULLM 0xffffffffu

typedef unsigned long long ull;

__device__ float g_M [NN];
__device__ float g_Ms[NN];
__device__ float g_Mi[NN];
__device__ float g_T [NN];
__device__ float g_W [NN];

// ---- f32x2 helpers ----
__device__ __forceinline__ ull pk2(float lo, float hi) {
    ull r; asm("mov.b64 %0,{%1,%2};" : "=l"(r) : "f"(lo), "f"(hi)); return r;
}
__device__ __forceinline__ float2 upk2(ull v) {
    float2 r; asm("mov.b64 {%0,%1},%2;" : "=f"(r.x), "=f"(r.y) : "l"(v)); return r;
}
__device__ __forceinline__ ull fma2(ull a, ull b, ull c) {
    ull r; asm("fma.rn.f32x2 %0,%1,%2,%3;" : "=l"(r) : "l"(a), "l"(b), "l"(c)); return r;
}
__device__ __forceinline__ ull mul2(ull a, ull b) {
    ull r; asm("mul.rn.f32x2 %0,%1,%2;" : "=l"(r) : "l"(a), "l"(b)); return r;
}
__device__ __forceinline__ float hadd2(ull v) { float2 f = upk2(v); return f.x + f.y; }
__device__ __forceinline__ float d4(float4 a, float4 b) {
    return fmaf(a.x, b.x, fmaf(a.y, b.y, fmaf(a.z, b.z, a.w * b.w)));
}
// collective: all 32 lanes must execute (full-mask shfl)
__device__ __forceinline__ void dots2(const ull* u, const ull* v, float& dd, float& apq) {
    ull U = mul2(u[0], u[0]), V = mul2(v[0], v[0]), P = mul2(u[0], v[0]);
#pragma unroll
    for (int i = 1; i < 4; i++) {
        U = fma2(u[i], u[i], U); V = fma2(v[i], v[i], V); P = fma2(u[i], v[i], P);
    }
    float d = hadd2(V) - hadd2(U);
    float p = hadd2(P);
#pragma unroll
    for (int k = 1; k < 8; k <<= 1) {
        d += __shfl_xor_sync(FULLM, d, k);
        p += __shfl_xor_sync(FULLM, p, k);
    }
    dd = d; apq = p;
}
__device__ __forceinline__ void rot_params2(float dd, float apq, float& c, float& s) {
    if (fabsf(apq) > 1e-34f) {
        float tau = __fdividef(dd, 2.f * apq);
        float tt  = copysignf(1.f, tau) / (fabsf(tau) + sqrtf(1.f + tau * tau));
        c = rsqrtf(1.f + tt * tt);
        s = tt * c;
    } else { c = 1.f; s = 0.f; }
}
__device__ __forceinline__ void get_pair(int r, int k, int& p, int& q) {
    int a = (k == 0) ? 0 : 1 + (k - 1 + r) % 63;
    int b = 1 + (62 - k + r) % 63;
    p = a < b ? a : b;
    q = a < b ? b : a;
}

// ---- single-matrix helpers ----
__device__ __forceinline__ void load_g2s(const float* __restrict__ g, float* S) {
    for (int idx = threadIdx.x; idx < NN; idx += TPB)
        S[(idx >> 6) * LD + (idx & 63)] = g[idx];
}
__device__ __forceinline__ void store_s2g(const float* S, float* __restrict__ g) {
    for (int idx = threadIdx.x; idx < NN; idx += TPB)
        g[idx] = S[(idx >> 6) * LD + (idx & 63)];
}
__device__ __forceinline__ void sym_s(float* A) {
    for (int idx = threadIdx.x; idx < NN; idx += TPB) {
        int i = idx >> 6, j = idx & 63;
        if (i < j) {
            float v = 0.5f * (A[i * LD + j] + A[j * LD + i]);
            A[i * LD + j] = v; A[j * LD + i] = v;
        }
    }
}
__device__ __forceinline__ void smm(const float* A, const float* B, float* C) {
    int j = threadIdx.x & 63, ib = (threadIdx.x >> 6) << 4;
    float acc[16];
#pragma unroll
    for (int i = 0; i < 16; i++) acc[i] = 0.f;
    for (int k = 0; k < 64; k++) {
        float bv = B[k * LD + j];
#pragma unroll
        for (int i = 0; i < 16; i++) acc[i] = fmaf(A[(ib + i) * LD + k], bv, acc[i]);
    }
#pragma unroll
    for (int i = 0; i < 16; i++) C[(ib + i) * LD + j] = acc[i];
}
__device__ __forceinline__ void smm_bt(const float* A, const float* B, float* C) {
    int j = threadIdx.x & 63, ib = (threadIdx.x >> 6) << 4;
    float acc[16];
#pragma unroll
    for (int i = 0; i < 16; i++) acc[i] = 0.f;
    for (int k = 0; k < 64; k++) {
        float bv = B[j * LD + k];
#pragma unroll
        for (int i = 0; i < 16; i++) acc[i] = fmaf(A[(ib + i) * LD + k], bv, acc[i]);
    }
#pragma unroll
    for (int i = 0; i < 16; i++) C[(ib + i) * LD + j] = acc[i];
}
__device__ __forceinline__ void smm_glob(const float* A, const float* B, float* __restrict__ g) {
    int j = threadIdx.x & 63, ib = (threadIdx.x >> 6) << 4;
    float acc[16];
#pragma unroll
    for (int i = 0; i < 16; i++) acc[i] = 0.f;
    for (int k = 0; k < 64; k++) {
        float bv = B[k * LD + j];
#pragma unroll
        for (int i = 0; i < 16; i++) acc[i] = fmaf(A[(ib + i) * LD + k], bv, acc[i]);
    }
#pragma unroll
    for (int i = 0; i < 16; i++) g[(ib + i) * 64 + j] = acc[i];
}
__device__ __forceinline__ void scalecols(const float* V, const float* w, float* O) {
    for (int idx = threadIdx.x; idx < NN; idx += TPB) {
        int i = idx >> 6, k = idx & 63;
        O[i * LD + k] = V[i * LD + k] * w[k];
    }
}

__device__ void jacobi2s(float* A, float* V, int nsweeps) {
    int t = threadIdx.x;
    __shared__ float cs[32], sn[32];
    __shared__ uchar2 tab2[63 * 32];
    for (int idx = t; idx < 63 * 32; idx += TPB) {
        int r = idx >> 5, k = idx & 31, p, q;
        get_pair(r, k, p, q);
        tab2[idx] = make_uchar2((unsigned char)p, (unsigned char)q);
    }
    for (int idx = t; idx < NN; idx += TPB) {
        int i = idx >> 6, j = idx & 63;
        V[i * LD + j] = (i == j) ? 1.f : 0.f;
    }
    __syncthreads();
    for (int sw = 0; sw < nsweeps; ++sw)
        for (int r = 0; r < 63; ++r) {
            const uchar2* trow = tab2 + (r << 5);
            if (t < 32) {
                uchar2 pq = trow[t];
                int pl = pq.x * LD, ql = pq.y * LD;
                float app = A[pl + pq.x], aqq = A[ql + pq.y], apq = A[pl + pq.y];
                float c, s;
                if (fabsf(apq) < 1e-30f) { c = 1.f; s = 0.f; }
                else {
                    float tau = (aqq - app) / (2.f * apq);
                    float tt  = copysignf(1.f, tau) / (fabsf(tau) + sqrtf(1.f + tau * tau));
                    c = rsqrtf(1.f + tt * tt); s = tt * c;
                }
                cs[t] = c; sn[t] = s;
            }
            __syncthreads();
#pragma unroll
            for (int m = 0; m < 2048 / TPB; m++) {
                int w = t + m * TPB, k = w >> 6, j = w & 63;
                uchar2 pq = trow[k];
                int pl = pq.x * LD + j, ql = pq.y * LD + j;
                float c = cs[k], s = sn[k];
                float ap = A[pl], aq = A[ql];
                A[pl] = c * ap - s * aq;
                A[ql] = fmaf(s, ap, c * aq);
            }
            __syncthreads();
#pragma unroll
            for (int m = 0; m < 2048 / TPB; m++) {
                int w = t + m * TPB, k = w >> 6, i = w & 63;
                uchar2 pq = trow[k];
                int il = i * LD, pl = il + pq.x, ql = il + pq.y;
                float c = cs[k], s = sn[k];
                float ap = A[pl], aq = A[ql];
                A[pl] = c * ap - s * aq;
                A[ql] = fmaf(s, ap, c * aq);
                float vp = V[pl], vq = V[ql];
                V[pl] = c * vp - s * vq;
                V[ql] = fmaf(s, vp, c * vq);
            }
            __syncthreads();
        }
}

// ---- batch GEMMs ----
__device__ __forceinline__ void gemm_rr(const float* A, const float* B, float* C) {
    int j = threadIdx.x & 63, ib = (threadIdx.x >> 6) << 4;
    ull acc[16];
#pragma unroll
    for (int i = 0; i < 16; i++) acc[i] = 0ull;
    for (int k = 0; k < 64; k += 2) {
        ull b2 = pk2(B[k * BLD + j], B[(k + 1) * BLD + j]);
#pragma unroll
        for (int i = 0; i < 16; i++)
            acc[i] = fma2(*(const ull*)(A + (ib + i) * BLD + k), b2, acc[i]);
    }
#pragma unroll
    for (int i = 0; i < 16; i++) { float2 f = upk2(acc[i]); C[(ib + i) * BLD + j] = f.x + f.y; }
}
__device__ __forceinline__ void gemm_r2c(const float* A, const float* B, float* C) {
    int j = threadIdx.x & 63, ib = (threadIdx.x >> 6) << 4;
    ull acc[16];
#pragma unroll
    for (int i = 0; i < 16; i++) acc[i] = 0ull;
    for (int k = 0; k < 64; k += 2) {
        ull b2 = pk2(B[k * BLD + j], B[(k + 1) * BLD + j]);
#pragma unroll
        for (int i = 0; i < 16; i++)
            acc[i] = fma2(*(const ull*)(A + (ib + i) * BLD + k), b2, acc[i]);
    }
    float r[16];
#pragma unroll
    for (int i = 0; i < 16; i++) { float2 f = upk2(acc[i]); r[i] = f.x + f.y; }
    float4* dst = (float4*)(C + j * CST + ib);
    dst[0] = make_float4(r[0], r[1], r[2], r[3]);
    dst[1] = make_float4(r[4], r[5], r[6], r[7]);
    dst[2] = make_float4(r[8], r[9], r[10], r[11]);
    dst[3] = make_float4(r[12], r[13], r[14], r[15]);
}

__device__ __forceinline__ void colscale_log(const float* B, float* W) {
    int t = threadIdx.x, col = t >> 2, qc = t & 3;
    const float4* bc = (const float4*)(B + col * CST);
    float4 v0 = bc[qc * 4 + 0], v1 = bc[qc * 4 + 1];
    float4 v2 = bc[qc * 4 + 2], v3 = bc[qc * 4 + 3];
    float pn = d4(v0, v0) + d4(v1, v1) + d4(v2, v2) + d4(v3, v3);
    pn += __shfl_xor_sync(FULLM, pn, 1);
    pn += __shfl_xor_sync(FULLM, pn, 2);
    float n2 = fmaxf(pn, 1e-24f);
    float g = 0.5f * logf(n2) / n2;
    float4* wc = (float4*)(W + col * CST);
    v0.x *= g; v0.y *= g; v0.z *= g; v0.w *= g;
    v1.x *= g; v1.y *= g; v1.z *= g; v1.w *= g;
    v2.x *= g; v2.y *= g; v2.z *= g; v2.w *= g;
    v3.x *= g; v3.y *= g; v3.z *= g; v3.w *= g;
    wc[qc * 4 + 0] = v0; wc[qc * 4 + 1] = v1;
    wc[qc * 4 + 2] = v2; wc[qc * 4 + 3] = v3;
}
__device__ __forceinline__ void logm_atomic(const float* W, const float* B, float scale) {
    int j = threadIdx.x & 63, ib = (threadIdx.x >> 6) << 4;
    float acc[16];
#pragma unroll
    for (int i = 0; i < 16; i++) acc[i] = 0.f;
    for (int k = 0; k < 64; k++) {
        float bj = B[k * CST + j];
        const float4* wr = (const float4*)(W + k * CST + ib);
        float4 w0 = wr[0], w1 = wr[1], w2 = wr[2], w3 = wr[3];
        acc[0]  = fmaf(w0.x, bj, acc[0]);  acc[1]  = fmaf(w0.y, bj, acc[1]);
        acc[2]  = fmaf(w0.z, bj, acc[2]);  acc[3]  = fmaf(w0.w, bj, acc[3]);
        acc[4]  = fmaf(w1.x, bj, acc[4]);  acc[5]  = fmaf(w1.y, bj, acc[5]);
        acc[6]  = fmaf(w1.z, bj, acc[6]);  acc[7]  = fmaf(w1.w, bj, acc[7]);
        acc[8]  = fmaf(w2.x, bj, acc[8]);  acc[9]  = fmaf(w2.y, bj, acc[9]);
        acc[10] = fmaf(w2.z, bj, acc[10]); acc[11] = fmaf(w2.w, bj, acc[11]);
        acc[12] = fmaf(w3.x, bj, acc[12]); acc[13] = fmaf(w3.y, bj, acc[13]);
        acc[14] = fmaf(w3.z, bj, acc[14]); acc[15] = fmaf(w3.w, bj, acc[15]);
    }
#pragma unroll
    for (int i = 0; i < 16; i++) atomicAdd(&g_T[(ib + i) * 64 + j], acc[i] * scale);
}

// ---- kernels ----
__global__ void k_zero(int which) {
    int i = blockIdx.x * blockDim.x + threadIdx.x;
    if (i < NN) { if (which == 0) g_M[i] = 0.f; else g_T[i] = 0.f; }
}
__global__ void k_mean_acc(const float* __restrict__ data, int per_chunk, float inv_nb) {
    int e = blockIdx.x * blockDim.x + threadIdx.x;
    const float* p = data + (size_t)(blockIdx.y) * per_chunk * NN + e;
    float sum = 0.f;
#pragma unroll 8
    for (int i = 0; i < per_chunk; i++) sum += p[(size_t)i * NN];
    atomicAdd(&g_M[e], sum * inv_nb);
}
__global__ void __launch_bounds__(TPB) k_eig_M() {
    extern __shared__ float sm[];
    float* A = sm; float* V = sm + BUF; float* T1 = sm + 2 * BUF; float* T2 = sm + 3 * BUF;
    __shared__ float w1[64], w2[64];
    load_g2s(g_M, A); __syncthreads();
    sym_s(A); __syncthreads();
    jacobi2s(A, V, NSWEEP_S);
    int t = threadIdx.x;
    if (t < 64) {
        float w = fmaxf(A[t * LD + t], 1e-12f);
        w1[t] = sqrtf(w); w2[t] = rsqrtf(w);
    }
    __syncthreads();
    scalecols(V, w1, T1); __syncthreads();
    smm_bt(T1, V, T2);    __syncthreads();
    store_s2g(T2, g_Ms);  __syncthreads();
    scalecols(V, w2, T1); __syncthreads();
    smm_bt(T1, V, T2);    __syncthreads();
    store_s2g(T2, g_Mi);
}

// batch step: C = Mi*D*Mi; register odd-even one-sided Jacobi; T += logm(C)/nb
__global__ void __launch_bounds__(TPB, 4) k_batch_oe(const float* __restrict__ data,
                                                     float inv_nb, int nsweep) {
    extern __shared__ float sm[];
    float* s0 = sm;             // Mi(row) -> xL overlay -> W(col)
    float* s1 = sm + BUFB;      // D(row) -> C(col) -> B(col)
    float* s2 = sm + 2 * BUFB;  // temp(row) -> xR overlay
    __shared__ float2 prm[2][32];
    int t = threadIdx.x;
    size_t b = blockIdx.x;

    for (int idx = t; idx < NN; idx += TPB)
        s0[(idx >> 6) * BLD + (idx & 63)] = g_Mi[idx];
    const float* D = data + b * NN;
    for (int idx = t; idx < NN; idx += TPB)
        s1[(idx >> 6) * BLD + (idx & 63)] = D[idx];
    __syncthreads();
    gemm_rr(s0, s1, s2);    // s2 = Mi*D (row)
    __syncthreads();
    gemm_r2c(s2, s0, s1);   // s1 = C (col CST)
    __syncthreads();
    for (int idx = t; idx < NN; idx += TPB) {   // symmetrize
        int i = idx >> 6, j = idx & 63;
        if (i < j) {
            float v = 0.5f * (s1[i * CST + j] + s1[j * CST + i]);
            s1[i * CST + j] = v; s1[j * CST + i] = v;
        }
    }
    __syncthreads();

    // ---- load 2 columns per 8-lane group into registers ----
    int lane = t & 31, warp = t >> 5, grp = lane >> 3, sub = lane & 7;
    int G = warp * 4 + grp;
    ull cL[4], cR[4];
    {
        const ulonglong2* pc = (const ulonglong2*)(s1 + (2 * G) * CST);
        ulonglong2 q0 = pc[2 * sub], q1 = pc[2 * sub + 1];
        cL[0] = q0.x; cL[1] = q0.y; cL[2] = q1.x; cL[3] = q1.y;
        const ulonglong2* pd = (const ulonglong2*)(s1 + (2 * G + 1) * CST);
        q0 = pd[2 * sub]; q1 = pd[2 * sub + 1];
        cR[0] = q0.x; cR[1] = q0.y; cR[2] = q1.x; cR[3] = q1.y;
    }
    __syncthreads();   // s0/s2 freed for xbuf overlays

    const bool hasR = (G < 31);
    const bool hasL = (G > 0);
    int pb = 0;
    for (int sw = 0; sw < nsweep; ++sw)
        for (int rr = 0; rr < 32; ++rr) {
            {   // EVEN round: pair (2G, 2G+1), registers only, swap
                float dd, apq;
                dots2(cL, cR, dd, apq);
                float c, s;
                rot_params2(dd, apq, c, s);
                ull c2 = pk2(c, c), s2p = pk2(s, s), ns2 = pk2(-s, -s);
#pragma unroll
                for (int i = 0; i < 4; i++) {
                    ull u = cL[i], v = cR[i];
                    cL[i] = fma2(s2p, u, mul2(c2, v));
                    cR[i] = fma2(ns2, v, mul2(c2, u));
                }
            }
            {   // ODD round: pair (2G+1, 2G+2) via smem exchange + param relay
                float4* Lb = (float4*)(s0 + ((pb << 5) + G) * 64);
                float4* Rb = (float4*)(s2 + ((pb << 5) + G) * 64);
                Lb[sub]     = *(float4*)&cL[0];
                Lb[sub + 8] = *(float4*)&cL[2];
                Rb[sub]     = *(float4*)&cR[0];
                Rb[sub + 8] = *(float4*)&cR[2];
                __syncthreads();
                ull vR[4] = {0, 0, 0, 0}, uL[4] = {0, 0, 0, 0};
                if (hasR) {
                    const float4* p = (const float4*)(s0 + ((pb << 5) + G + 1) * 64);
                    *(float4*)&vR[0] = p[sub];
                    *(float4*)&vR[2] = p[sub + 8];
                }
                if (hasL) {
                    const float4* p = (const float4*)(s2 + ((pb << 5) + G - 1) * 64);
                    *(float4*)&uL[0] = p[sub];
                    *(float4*)&uL[2] = p[sub + 8];
                }
                float dd, apq;
                dots2(cR, vR, dd, apq);   // collective (vR=0 -> identity)
                float c, s;
                rot_params2(dd, apq, c, s);
                if (sub == 0) prm[pb][G] = make_float2(c, s);
                __syncthreads();
                if (hasR) {
                    ull c2 = pk2(c, c), s2p = pk2(s, s);
#pragma unroll
                    for (int i = 0; i < 4; i++)
                        cR[i] = fma2(s2p, cR[i], mul2(c2, vR[i]));
                }
                if (hasL) {
                    float2 ps = prm[pb][G - 1];
                    ull cl2 = pk2(ps.x, ps.x), nsl2 = pk2(-ps.y, -ps.y);
#pragma unroll
                    for (int i = 0; i < 4; i++)
                        cL[i] = fma2(nsl2, cL[i], mul2(cl2, uL[i]));
                }
                pb ^= 1;
            }
        }

    // store columns back to s1 (col CST), permutation irrelevant
    {
        ulonglong2* pc = (ulonglong2*)(s1 + (2 * G) * CST);
        pc[2 * sub]     = make_ulonglong2(cL[0], cL[1]);
        pc[2 * sub + 1] = make_ulonglong2(cL[2], cL[3]);
        ulonglong2* pd = (ulonglong2*)(s1 + (2 * G + 1) * CST);
        pd[2 * sub]     = make_ulonglong2(cR[0], cR[1]);
        pd[2 * sub + 1] = make_ulonglong2(cR[2], cR[3]);
    }
    __syncthreads();
    colscale_log(s1, s0);
    __syncthreads();
    logm_atomic(s0, s1, inv_nb);
}

__global__ void __launch_bounds__(TPB) k_update_M() {
    extern __shared__ float sm[];
    float* A = sm; float* V = sm + BUF; float* T1 = sm + 2 * BUF; float* T2 = sm + 3 * BUF;
    __shared__ float ew[64];
    load_g2s(g_T, A); __syncthreads();
    sym_s(A); __syncthreads();
    jacobi2s(A, V, NSWEEP_S);
    int t = threadIdx.x;
    if (t < 64) ew[t] = expf(A[t * LD + t]);
    __syncthreads();
    scalecols(V, ew, T1); __syncthreads();
    smm_bt(T1, V, T2);    __syncthreads();
    load_g2s(g_Ms, A);    __syncthreads();
    smm(A, T2, T1);       __syncthreads();
    smm_glob(T1, A, g_M);
}
__global__ void __launch_bounds__(TPB) k_bias(const float* __restrict__ bias) {
    extern __shared__ float sm[];
    float* A = sm; float* V = sm + BUF; float* T1 = sm + 2 * BUF; float* T2 = sm + 3 * BUF;
    __shared__ float ew[64];
    int t = threadIdx.x;
    for (int idx = t; idx < NN; idx += TPB) {
        int i = idx >> 6, j = idx & 63;
        A[i * LD + j] = 0.5f * (bias[i * 64 + j] + bias[j * 64 + i]);
    }
    __syncthreads();
    jacobi2s(A, V, NSWEEP_S);
    if (t < 64) ew[t] = expf(0.5f * A[t * LD + t]);
    __syncthreads();
    scalecols(V, ew, T1); __syncthreads();
    smm_bt(T1, V, T2);    __syncthreads();
    load_g2s(g_Mi, A);    __syncthreads();
    smm_glob(T2, A, g_W);
}
__global__ void __launch_bounds__(TPB, 4) k_final(const float* __restrict__ data,
                                                  float* __restrict__ out) {
    extern __shared__ float sm[];
    float* sW = sm; float* sD = sm + BUFB; float* sT = sm + 2 * BUFB;
    size_t b = blockIdx.x;
    int t = threadIdx.x;
    for (int idx = t; idx < NN; idx += TPB)
        sW[(idx >> 6) * BLD + (idx & 63)] = g_W[idx];
    const float* D = data + b * NN;
    for (int idx = t; idx < NN; idx += TPB)
        sD[(idx >> 6) * BLD + (idx & 63)] = D[idx];
    __syncthreads();
    gemm_rr(sW, sD, sT);
    __syncthreads();
    int j = t & 63, ib = (t >> 6) << 4;
    ull acc[16];
#pragma unroll
    for (int i = 0; i < 16; i++) acc[i] = 0ull;
    for (int k = 0; k < 64; k += 2) {
        ull b2 = *(const ull*)(sW + j * BLD + k);
#pragma unroll
        for (int i = 0; i < 16; i++)
            acc[i] = fma2(*(const ull*)(sT + (ib + i) * BLD + k), b2, acc[i]);
    }
    float* o = out + b * NN;
#pragma unroll
    for (int i = 0; i < 16; i++) { float2 f = upk2(acc[i]); o[(ib + i) * 64 + j] = f.x + f.y; }
}

// ---------------------------------------------------------------------------
extern "C" void kernel_launch(void* const* d_in, const int* in_sizes, int n_in,
                              void* d_out, int out_size) {
    const float* data;
    const float* bias;
    int nb;
    if (in_sizes[0] >= in_sizes[1]) {
        data = (const float*)d_in[0]; bias = (const float*)d_in[1];
        nb = in_sizes[0] / NN;
    } else {
        data = (const float*)d_in[1]; bias = (const float*)d_in[0];
        nb = in_sizes[1] / NN;
    }
    float* out = (float*)d_out;
    float inv_nb = 1.0f / (float)nb;

    size_t smemS = 4 * BUF  * sizeof(float);
    size_t smemB = 3 * BUFB * sizeof(float);
    cudaFuncSetAttribute(k_eig_M,    cudaFuncAttributeMaxDynamicSharedMemorySize, (int)smemS);
    cudaFuncSetAttribute(k_batch_oe, cudaFuncAttributeMaxDynamicSharedMemorySize, (int)smemB);
    cudaFuncSetAttribute(k_update_M, cudaFuncAttributeMaxDynamicSharedMemorySize, (int)smemS);
    cudaFuncSetAttribute(k_bias,     cudaFuncAttributeMaxDynamicSharedMemorySize, (int)smemS);
    cudaFuncSetAttribute(k_final,    cudaFuncAttributeMaxDynamicSharedMemorySize, (int)smemB);

    k_zero<<<16, 256>>>(0);
    {
        int nchunk = 64;
        while (nchunk > 1 && (nb % nchunk) != 0) nchunk >>= 1;
        int per_chunk = nb / nchunk;
        dim3 g(NN / 256, nchunk);
        k_mean_acc<<<g, 256>>>(data, per_chunk, inv_nb);
    }

    // Karcher iterations: sweep schedule 6/6/7 (early residuals are damped)
    const int sweeps[3] = {6, 6, 7};
    for (int it = 0; it < 3; ++it) {
        k_eig_M<<<1, TPB, smemS>>>();
        k_zero<<<16, 256>>>(1);
        k_batch_oe<<<nb, TPB, smemB>>>(data, inv_nb, sweeps[it]);
        k_update_M<<<1, TPB, smemS>>>();
    }

    k_eig_M<<<1, TPB, smemS>>>();
    k_bias<<<1, TPB, smemS>>>(bias);
    k_final<<<nb, TPB, smemB>>>(data, out);
}

// round 16
// speedup vs baseline: 1.1506x; 1.0288x over previous
#include <cuda_runtime.h>
#include <cuda_bf16.h>
#include <math.h>

// ============================================================================
// BatchNormSPDMean R16: sweep schedule 5/6/7 + fused logm epilogue
// (logm = B diag(g) B^T with g folded into broadcast; f32x2 row-pairs;
//  colscale pass eliminated).
// ============================================================================

#define NN 4096
#define LD 65        // single-matrix kernels row stride
#define BLD 66       // batch row-major stride
#define CST 68       // batch col-major column stride
#define BUFB 4352
#define NSWEEP_S 10
#define TPB 256
#define BUF 4160
#define FULLM 0xffffffffu

typedef unsigned long long ull;

__device__ float g_M [NN];
__device__ float g_Ms[NN];
__device__ float g_Mi[NN];
__device__ float g_T [NN];
__device__ float g_W [NN];

// ---- f32x2 helpers ----
__device__ __forceinline__ ull pk2(float lo, float hi) {
    ull r; asm("mov.b64 %0,{%1,%2};" : "=l"(r) : "f"(lo), "f"(hi)); return r;
}
__device__ __forceinline__ float2 upk2(ull v) {
    float2 r; asm("mov.b64 {%0,%1},%2;" : "=f"(r.x), "=f"(r.y) : "l"(v)); return r;
}
__device__ __forceinline__ ull fma2(ull a, ull b, ull c) {
    ull r; asm("fma.rn.f32x2 %0,%1,%2,%3;" : "=l"(r) : "l"(a), "l"(b), "l"(c)); return r;
}
__device__ __forceinline__ ull mul2(ull a, ull b) {
    ull r; asm("mul.rn.f32x2 %0,%1,%2;" : "=l"(r) : "l"(a), "l"(b)); return r;
}
__device__ __forceinline__ float hadd2(ull v) { float2 f = upk2(v); return f.x + f.y; }
__device__ __forceinline__ float d4(float4 a, float4 b) {
    return fmaf(a.x, b.x, fmaf(a.y, b.y, fmaf(a.z, b.z, a.w * b.w)));
}
// collective: all 32 lanes must execute (full-mask shfl)
__device__ __forceinline__ void dots2(const ull* u, const ull* v, float& dd, float& apq) {
    ull U = mul2(u[0], u[0]), V = mul2(v[0], v[0]), P = mul2(u[0], v[0]);
#pragma unroll
    for (int i = 1; i < 4; i++) {
        U = fma2(u[i], u[i], U); V = fma2(v[i], v[i], V); P = fma2(u[i], v[i], P);
    }
    float d = hadd2(V) - hadd2(U);
    float p = hadd2(P);
#pragma unroll
    for (int k = 1; k < 8; k <<= 1) {
        d += __shfl_xor_sync(FULLM, d, k);
        p += __shfl_xor_sync(FULLM, p, k);
    }
    dd = d; apq = p;
}
__device__ __forceinline__ void rot_params2(float dd, float apq, float& c, float& s) {
    if (fabsf(apq) > 1e-34f) {
        float tau = __fdividef(dd, 2.f * apq);
        float tt  = copysignf(1.f, tau) / (fabsf(tau) + sqrtf(1.f + tau * tau));
        c = rsqrtf(1.f + tt * tt);
        s = tt * c;
    } else { c = 1.f; s = 0.f; }
}
__device__ __forceinline__ void get_pair(int r, int k, int& p, int& q) {
    int a = (k == 0) ? 0 : 1 + (k - 1 + r) % 63;
    int b = 1 + (62 - k + r) % 63;
    p = a < b ? a : b;
    q = a < b ? b : a;
}

// ---- single-matrix helpers ----
__device__ __forceinline__ void load_g2s(const float* __restrict__ g, float* S) {
    for (int idx = threadIdx.x; idx < NN; idx += TPB)
        S[(idx >> 6) * LD + (idx & 63)] = g[idx];
}
__device__ __forceinline__ void store_s2g(const float* S, float* __restrict__ g) {
    for (int idx = threadIdx.x; idx < NN; idx += TPB)
        g[idx] = S[(idx >> 6) * LD + (idx & 63)];
}
__device__ __forceinline__ void sym_s(float* A) {
    for (int idx = threadIdx.x; idx < NN; idx += TPB) {
        int i = idx >> 6, j = idx & 63;
        if (i < j) {
            float v = 0.5f * (A[i * LD + j] + A[j * LD + i]);
            A[i * LD + j] = v; A[j * LD + i] = v;
        }
    }
}
__device__ __forceinline__ void smm(const float* A, const float* B, float* C) {
    int j = threadIdx.x & 63, ib = (threadIdx.x >> 6) << 4;
    float acc[16];
#pragma unroll
    for (int i = 0; i < 16; i++) acc[i] = 0.f;
    for (int k = 0; k < 64; k++) {
        float bv = B[k * LD + j];
#pragma unroll
        for (int i = 0; i < 16; i++) acc[i] = fmaf(A[(ib + i) * LD + k], bv, acc[i]);
    }
#pragma unroll
    for (int i = 0; i < 16; i++) C[(ib + i) * LD + j] = acc[i];
}
__device__ __forceinline__ void smm_bt(const float* A, const float* B, float* C) {
    int j = threadIdx.x & 63, ib = (threadIdx.x >> 6) << 4;
    float acc[16];
#pragma unroll
    for (int i = 0; i < 16; i++) acc[i] = 0.f;
    for (int k = 0; k < 64; k++) {
        float bv = B[j * LD + k];
#pragma unroll
        for (int i = 0; i < 16; i++) acc[i] = fmaf(A[(ib + i) * LD + k], bv, acc[i]);
    }
#pragma unroll
    for (int i = 0; i < 16; i++) C[(ib + i) * LD + j] = acc[i];
}
__device__ __forceinline__ void smm_glob(const float* A, const float* B, float* __restrict__ g) {
    int j = threadIdx.x & 63, ib = (threadIdx.x >> 6) << 4;
    float acc[16];
#pragma unroll
    for (int i = 0; i < 16; i++) acc[i] = 0.f;
    for (int k = 0; k < 64; k++) {
        float bv = B[k * LD + j];
#pragma unroll
        for (int i = 0; i < 16; i++) acc[i] = fmaf(A[(ib + i) * LD + k], bv, acc[i]);
    }
#pragma unroll
    for (int i = 0; i < 16; i++) g[(ib + i) * 64 + j] = acc[i];
}
__device__ __forceinline__ void scalecols(const float* V, const float* w, float* O) {
    for (int idx = threadIdx.x; idx < NN; idx += TPB) {
        int i = idx >> 6, k = idx & 63;
        O[i * LD + k] = V[i * LD + k] * w[k];
    }
}

__device__ void jacobi2s(float* A, float* V, int nsweeps) {
    int t = threadIdx.x;
    __shared__ float cs[32], sn[32];
    __shared__ uchar2 tab2[63 * 32];
    for (int idx = t; idx < 63 * 32; idx += TPB) {
        int r = idx >> 5, k = idx & 31, p, q;
        get_pair(r, k, p, q);
        tab2[idx] = make_uchar2((unsigned char)p, (unsigned char)q);
    }
    for (int idx = t; idx < NN; idx += TPB) {
        int i = idx >> 6, j = idx & 63;
        V[i * LD + j] = (i == j) ? 1.f : 0.f;
    }
    __syncthreads();
    for (int sw = 0; sw < nsweeps; ++sw)
        for (int r = 0; r < 63; ++r) {
            const uchar2* trow = tab2 + (r << 5);
            if (t < 32) {
                uchar2 pq = trow[t];
                int pl = pq.x * LD, ql = pq.y * LD;
                float app = A[pl + pq.x], aqq = A[ql + pq.y], apq = A[pl + pq.y];
                float c, s;
                if (fabsf(apq) < 1e-30f) { c = 1.f; s = 0.f; }
                else {
                    float tau = (aqq - app) / (2.f * apq);
                    float tt  = copysignf(1.f, tau) / (fabsf(tau) + sqrtf(1.f + tau * tau));
                    c = rsqrtf(1.f + tt * tt); s = tt * c;
                }
                cs[t] = c; sn[t] = s;
            }
            __syncthreads();
#pragma unroll
            for (int m = 0; m < 2048 / TPB; m++) {
                int w = t + m * TPB, k = w >> 6, j = w & 63;
                uchar2 pq = trow[k];
                int pl = pq.x * LD + j, ql = pq.y * LD + j;
                float c = cs[k], s = sn[k];
                float ap = A[pl], aq = A[ql];
                A[pl] = c * ap - s * aq;
                A[ql] = fmaf(s, ap, c * aq);
            }
            __syncthreads();
#pragma unroll
            for (int m = 0; m < 2048 / TPB; m++) {
                int w = t + m * TPB, k = w >> 6, i = w & 63;
                uchar2 pq = trow[k];
                int il = i * LD, pl = il + pq.x, ql = il + pq.y;
                float c = cs[k], s = sn[k];
                float ap = A[pl], aq = A[ql];
                A[pl] = c * ap - s * aq;
                A[ql] = fmaf(s, ap, c * aq);
                float vp = V[pl], vq = V[ql];
                V[pl] = c * vp - s * vq;
                V[ql] = fmaf(s, vp, c * vq);
            }
            __syncthreads();
        }
}

// ---- batch GEMMs ----
__device__ __forceinline__ void gemm_rr(const float* A, const float* B, float* C) {
    int j = threadIdx.x & 63, ib = (threadIdx.x >> 6) << 4;
    ull acc[16];
#pragma unroll
    for (int i = 0; i < 16; i++) acc[i] = 0ull;
    for (int k = 0; k < 64; k += 2) {
        ull b2 = pk2(B[k * BLD + j], B[(k + 1) * BLD + j]);
#pragma unroll
        for (int i = 0; i < 16; i++)
            acc[i] = fma2(*(const ull*)(A + (ib + i) * BLD + k), b2, acc[i]);
    }
#pragma unroll
    for (int i = 0; i < 16; i++) { float2 f = upk2(acc[i]); C[(ib + i) * BLD + j] = f.x + f.y; }
}
__device__ __forceinline__ void gemm_r2c(const float* A, const float* B, float* C) {
    int j = threadIdx.x & 63, ib = (threadIdx.x >> 6) << 4;
    ull acc[16];
#pragma unroll
    for (int i = 0; i < 16; i++) acc[i] = 0ull;
    for (int k = 0; k < 64; k += 2) {
        ull b2 = pk2(B[k * BLD + j], B[(k + 1) * BLD + j]);
#pragma unroll
        for (int i = 0; i < 16; i++)
            acc[i] = fma2(*(const ull*)(A + (ib + i) * BLD + k), b2, acc[i]);
    }
    float r[16];
#pragma unroll
    for (int i = 0; i < 16; i++) { float2 f = upk2(acc[i]); r[i] = f.x + f.y; }
    float4* dst = (float4*)(C + j * CST + ib);
    dst[0] = make_float4(r[0], r[1], r[2], r[3]);
    dst[1] = make_float4(r[4], r[5], r[6], r[7]);
    dst[2] = make_float4(r[8], r[9], r[10], r[11]);
    dst[3] = make_float4(r[12], r[13], r[14], r[15]);
}

// fused logm epilogue: g_T += scale * B diag(g) B^T, g_k = 0.5*log(n2_k)/n2_k
__device__ __forceinline__ void logm_fused_atomic(const float* B, float* sg, float scale) {
    int t = threadIdx.x;
    {   // per-column g into sg (4 threads per column)
        int col = t >> 2, qc = t & 3;
        const float4* bc = (const float4*)(B + col * CST);
        float4 v0 = bc[qc * 4 + 0], v1 = bc[qc * 4 + 1];
        float4 v2 = bc[qc * 4 + 2], v3 = bc[qc * 4 + 3];
        float pn = d4(v0, v0) + d4(v1, v1) + d4(v2, v2) + d4(v3, v3);
        pn += __shfl_xor_sync(FULLM, pn, 1);
        pn += __shfl_xor_sync(FULLM, pn, 2);
        float n2 = fmaxf(pn, 1e-24f);
        if (qc == 0) sg[col] = 0.5f * logf(n2) / n2;
    }
    __syncthreads();
    // logm[i][j] = sum_k g_k B[i,k] B[j,k]; f32x2 over adjacent-row pairs
    int j = t & 63, ib = (t >> 6) << 4;
    ull acc[8];
#pragma unroll
    for (int p = 0; p < 8; p++) acc[p] = 0ull;
    for (int k = 0; k < 64; k++) {
        float bj = B[k * CST + j] * sg[k];
        ull bj2 = pk2(bj, bj);
        const ulonglong2* wr = (const ulonglong2*)(B + k * CST + ib);
        ulonglong2 w0 = wr[0], w1 = wr[1];
        acc[0] = fma2(w0.x, bj2, acc[0]);
        acc[1] = fma2(w0.y, bj2, acc[1]);
        acc[2] = fma2(w1.x, bj2, acc[2]);
        acc[3] = fma2(w1.y, bj2, acc[3]);
        ulonglong2 w2 = wr[2], w3 = wr[3];
        acc[4] = fma2(w2.x, bj2, acc[4]);
        acc[5] = fma2(w2.y, bj2, acc[5]);
        acc[6] = fma2(w3.x, bj2, acc[6]);
        acc[7] = fma2(w3.y, bj2, acc[7]);
    }
#pragma unroll
    for (int p = 0; p < 8; p++) {
        float2 f = upk2(acc[p]);
        atomicAdd(&g_T[(ib + 2 * p) * 64 + j],     f.x * scale);
        atomicAdd(&g_T[(ib + 2 * p + 1) * 64 + j], f.y * scale);
    }
}

// ---- kernels ----
__global__ void k_zero(int which) {
    int i = blockIdx.x * blockDim.x + threadIdx.x;
    if (i < NN) { if (which == 0) g_M[i] = 0.f; else g_T[i] = 0.f; }
}
__global__ void k_mean_acc(const float* __restrict__ data, int per_chunk, float inv_nb) {
    int e = blockIdx.x * blockDim.x + threadIdx.x;
    const float* p = data + (size_t)(blockIdx.y) * per_chunk * NN + e;
    float sum = 0.f;
#pragma unroll 8
    for (int i = 0; i < per_chunk; i++) sum += p[(size_t)i * NN];
    atomicAdd(&g_M[e], sum * inv_nb);
}
__global__ void __launch_bounds__(TPB) k_eig_M() {
    extern __shared__ float sm[];
    float* A = sm; float* V = sm + BUF; float* T1 = sm + 2 * BUF; float* T2 = sm + 3 * BUF;
    __shared__ float w1[64], w2[64];
    load_g2s(g_M, A); __syncthreads();
    sym_s(A); __syncthreads();
    jacobi2s(A, V, NSWEEP_S);
    int t = threadIdx.x;
    if (t < 64) {
        float w = fmaxf(A[t * LD + t], 1e-12f);
        w1[t] = sqrtf(w); w2[t] = rsqrtf(w);
    }
    __syncthreads();
    scalecols(V, w1, T1); __syncthreads();
    smm_bt(T1, V, T2);    __syncthreads();
    store_s2g(T2, g_Ms);  __syncthreads();
    scalecols(V, w2, T1); __syncthreads();
    smm_bt(T1, V, T2);    __syncthreads();
    store_s2g(T2, g_Mi);
}

// batch step: C = Mi*D*Mi; register odd-even one-sided Jacobi; T += logm(C)/nb
__global__ void __launch_bounds__(TPB, 4) k_batch_oe(const float* __restrict__ data,
                                                     float inv_nb, int nsweep) {
    extern __shared__ float sm[];
    float* s0 = sm;             // Mi(row) -> xL overlay
    float* s1 = sm + BUFB;      // D(row) -> C(col) -> B(col)
    float* s2 = sm + 2 * BUFB;  // temp(row) -> xR overlay
    __shared__ float2 prm[2][32];
    __shared__ float sg[64];
    int t = threadIdx.x;
    size_t b = blockIdx.x;

    for (int idx = t; idx < NN; idx += TPB)
        s0[(idx >> 6) * BLD + (idx & 63)] = g_Mi[idx];
    const float* D = data + b * NN;
    for (int idx = t; idx < NN; idx += TPB)
        s1[(idx >> 6) * BLD + (idx & 63)] = D[idx];
    __syncthreads();
    gemm_rr(s0, s1, s2);    // s2 = Mi*D (row)
    __syncthreads();
    gemm_r2c(s2, s0, s1);   // s1 = C (col CST)
    __syncthreads();
    for (int idx = t; idx < NN; idx += TPB) {   // symmetrize
        int i = idx >> 6, j = idx & 63;
        if (i < j) {
            float v = 0.5f * (s1[i * CST + j] + s1[j * CST + i]);
            s1[i * CST + j] = v; s1[j * CST + i] = v;
        }
    }
    __syncthreads();

    // ---- load 2 columns per 8-lane group into registers ----
    int lane = t & 31, warp = t >> 5, grp = lane >> 3, sub = lane & 7;
    int G = warp * 4 + grp;
    ull cL[4], cR[4];
    {
        const ulonglong2* pc = (const ulonglong2*)(s1 + (2 * G) * CST);
        ulonglong2 q0 = pc[2 * sub], q1 = pc[2 * sub + 1];
        cL[0] = q0.x; cL[1] = q0.y; cL[2] = q1.x; cL[3] = q1.y;
        const ulonglong2* pd = (const ulonglong2*)(s1 + (2 * G + 1) * CST);
        q0 = pd[2 * sub]; q1 = pd[2 * sub + 1];
        cR[0] = q0.x; cR[1] = q0.y; cR[2] = q1.x; cR[3] = q1.y;
    }
    __syncthreads();   // s0/s2 freed for xbuf overlays

    const bool hasR = (G < 31);
    const bool hasL = (G > 0);
    int pb = 0;
    for (int sw = 0; sw < nsweep; ++sw)
        for (int rr = 0; rr < 32; ++rr) {
            {   // EVEN round: pair (2G, 2G+1), registers only, swap
                float dd, apq;
                dots2(cL, cR, dd, apq);
                float c, s;
                rot_params2(dd, apq, c, s);
                ull c2 = pk2(c, c), s2p = pk2(s, s), ns2 = pk2(-s, -s);
#pragma unroll
                for (int i = 0; i < 4; i++) {
                    ull u = cL[i], v = cR[i];
                    cL[i] = fma2(s2p, u, mul2(c2, v));
                    cR[i] = fma2(ns2, v, mul2(c2, u));
                }
            }
            {   // ODD round: pair (2G+1, 2G+2) via smem exchange + param relay
                float4* Lb = (float4*)(s0 + ((pb << 5) + G) * 64);
                float4* Rb = (float4*)(s2 + ((pb << 5) + G) * 64);
                Lb[sub]     = *(float4*)&cL[0];
                Lb[sub + 8] = *(float4*)&cL[2];
                Rb[sub]     = *(float4*)&cR[0];
                Rb[sub + 8] = *(float4*)&cR[2];
                __syncthreads();
                ull vR[4] = {0, 0, 0, 0}, uL[4] = {0, 0, 0, 0};
                if (hasR) {
                    const float4* p = (const float4*)(s0 + ((pb << 5) + G + 1) * 64);
                    *(float4*)&vR[0] = p[sub];
                    *(float4*)&vR[2] = p[sub + 8];
                }
                if (hasL) {
                    const float4* p = (const float4*)(s2 + ((pb << 5) + G - 1) * 64);
                    *(float4*)&uL[0] = p[sub];
                    *(float4*)&uL[2] = p[sub + 8];
                }
                float dd, apq;
                dots2(cR, vR, dd, apq);   // collective (vR=0 -> identity)
                float c, s;
                rot_params2(dd, apq, c, s);
                if (sub == 0) prm[pb][G] = make_float2(c, s);
                __syncthreads();
                if (hasR) {
                    ull c2 = pk2(c, c), s2p = pk2(s, s);
#pragma unroll
                    for (int i = 0; i < 4; i++)
                        cR[i] = fma2(s2p, cR[i], mul2(c2, vR[i]));
                }
                if (hasL) {
                    float2 ps = prm[pb][G - 1];
                    ull cl2 = pk2(ps.x, ps.x), nsl2 = pk2(-ps.y, -ps.y);
#pragma unroll
                    for (int i = 0; i < 4; i++)
                        cL[i] = fma2(nsl2, cL[i], mul2(cl2, uL[i]));
                }
                pb ^= 1;
            }
        }

    // store columns back to s1 (col CST), permutation irrelevant
    {
        ulonglong2* pc = (ulonglong2*)(s1 + (2 * G) * CST);
        pc[2 * sub]     = make_ulonglong2(cL[0], cL[1]);
        pc[2 * sub + 1] = make_ulonglong2(cL[2], cL[3]);
        ulonglong2* pd = (ulonglong2*)(s1 + (2 * G + 1) * CST);
        pd[2 * sub]     = make_ulonglong2(cR[0], cR[1]);
        pd[2 * sub + 1] = make_ulonglong2(cR[2], cR[3]);
    }
    __syncthreads();
    logm_fused_atomic(s1, sg, inv_nb);
}

__global__ void __launch_bounds__(TPB) k_update_M() {
    extern __shared__ float sm[];
    float* A = sm; float* V = sm + BUF; float* T1 = sm + 2 * BUF; float* T2 = sm + 3 * BUF;
    __shared__ float ew[64];
    load_g2s(g_T, A); __syncthreads();
    sym_s(A); __syncthreads();
    jacobi2s(A, V, NSWEEP_S);
    int t = threadIdx.x;
    if (t < 64) ew[t] = expf(A[t * LD + t]);
    __syncthreads();
    scalecols(V, ew, T1); __syncthreads();
    smm_bt(T1, V, T2);    __syncthreads();
    load_g2s(g_Ms, A);    __syncthreads();
    smm(A, T2, T1);       __syncthreads();
    smm_glob(T1, A, g_M);
}
__global__ void __launch_bounds__(TPB) k_bias(const float* __restrict__ bias) {
    extern __shared__ float sm[];
    float* A = sm; float* V = sm + BUF; float* T1 = sm + 2 * BUF; float* T2 = sm + 3 * BUF;
    __shared__ float ew[64];
    int t = threadIdx.x;
    for (int idx = t; idx < NN; idx += TPB) {
        int i = idx >> 6, j = idx & 63;
        A[i * LD + j] = 0.5f * (bias[i * 64 + j] + bias[j * 64 + i]);
    }
    __syncthreads();
    jacobi2s(A, V, NSWEEP_S);
    if (t < 64) ew[t] = expf(0.5f * A[t * LD + t]);
    __syncthreads();
    scalecols(V, ew, T1); __syncthreads();
    smm_bt(T1, V, T2);    __syncthreads();
    load_g2s(g_Mi, A);    __syncthreads();
    smm_glob(T2, A, g_W);
}
__global__ void __launch_bounds__(TPB, 4) k_final(const float* __restrict__ data,
                                                  float* __restrict__ out) {
    extern __shared__ float sm[];
    float* sW = sm; float* sD = sm + BUFB; float* sT = sm + 2 * BUFB;
    size_t b = blockIdx.x;
    int t = threadIdx.x;
    for (int idx = t; idx < NN; idx += TPB)
        sW[(idx >> 6) * BLD + (idx & 63)] = g_W[idx];
    const float* D = data + b * NN;
    for (int idx = t; idx < NN; idx += TPB)
        sD[(idx >> 6) * BLD + (idx & 63)] = D[idx];
    __syncthreads();
    gemm_rr(sW, sD, sT);
    __syncthreads();
    int j = t & 63, ib = (t >> 6) << 4;
    ull acc[16];
#pragma unroll
    for (int i = 0; i < 16; i++) acc[i] = 0ull;
    for (int k = 0; k < 64; k += 2) {
        ull b2 = *(const ull*)(sW + j * BLD + k);
#pragma unroll
        for (int i = 0; i < 16; i++)
            acc[i] = fma2(*(const ull*)(sT + (ib + i) * BLD + k), b2, acc[i]);
    }
    float* o = out + b * NN;
#pragma unroll
    for (int i = 0; i < 16; i++) { float2 f = upk2(acc[i]); o[(ib + i) * 64 + j] = f.x + f.y; }
}

// ---------------------------------------------------------------------------
extern "C" void kernel_launch(void* const* d_in, const int* in_sizes, int n_in,
                              void* d_out, int out_size) {
    const float* data;
    const float* bias;
    int nb;
    if (in_sizes[0] >= in_sizes[1]) {
        data = (const float*)d_in[0]; bias = (const float*)d_in[1];
        nb = in_sizes[0] / NN;
    } else {
        data = (const float*)d_in[1]; bias = (const float*)d_in[0];
        nb = in_sizes[1] / NN;
    }
    float* out = (float*)d_out;
    float inv_nb = 1.0f / (float)nb;

    size_t smemS = 4 * BUF  * sizeof(float);
    size_t smemB = 3 * BUFB * sizeof(float);
    cudaFuncSetAttribute(k_eig_M,    cudaFuncAttributeMaxDynamicSharedMemorySize, (int)smemS);
    cudaFuncSetAttribute(k_batch_oe, cudaFuncAttributeMaxDynamicSharedMemorySize, (int)smemB);
    cudaFuncSetAttribute(k_update_M, cudaFuncAttributeMaxDynamicSharedMemorySize, (int)smemS);
    cudaFuncSetAttribute(k_bias,     cudaFuncAttributeMaxDynamicSharedMemorySize, (int)smemS);
    cudaFuncSetAttribute(k_final,    cudaFuncAttributeMaxDynamicSharedMemorySize, (int)smemB);

    k_zero<<<16, 256>>>(0);
    {
        int nchunk = 64;
        while (nchunk > 1 && (nb % nchunk) != 0) nchunk >>= 1;
        int per_chunk = nb / nchunk;
        dim3 g(NN / 256, nchunk);
        k_mean_acc<<<g, 256>>>(data, per_chunk, inv_nb);
    }

    // Karcher iterations: sweep schedule 5/6/7 (early residuals are damped)
    const int sweeps[3] = {5, 6, 7};
    for (int it = 0; it < 3; ++it) {
        k_eig_M<<<1, TPB, smemS>>>();
        k_zero<<<16, 256>>>(1);
        k_batch_oe<<<nb, TPB, smemB>>>(data, inv_nb, sweeps[it]);
        k_update_M<<<1, TPB, smemS>>>();
    }

    k_eig_M<<<1, TPB, smemS>>>();
    k_bias<<<1, TPB, smemS>>>(bias);
    k_final<<<nb, TPB, smemB>>>(data, out);
}

// round 17
// speedup vs baseline: 1.3373x; 1.1623x over previous
#include <cuda_runtime.h>
#include <cuda_bf16.h>
#include <math.h>

// ============================================================================
// BatchNormSPDMean R17: sweeps 5/5/7, NSWEEP_S 8, g_T zeroing folded into
// k_eig_M, bias eigh runs concurrently (block 1 of final eig kernel).
// ============================================================================

#define NN 4096
#define LD 65
#define BLD 66
#define CST 68
#define BUFB 4352
#define NSWEEP_S 8
#define TPB 256
#define BUF 4160
#define FULLM 0xffffffffu

typedef unsigned long long ull;

__device__ float g_M [NN];
__device__ float g_Ms[NN];
__device__ float g_Mi[NN];
__device__ float g_T [NN];
__device__ float g_W [NN];
__device__ float g_S [NN];

// ---- f32x2 helpers ----
__device__ __forceinline__ ull pk2(float lo, float hi) {
    ull r; asm("mov.b64 %0,{%1,%2};" : "=l"(r) : "f"(lo), "f"(hi)); return r;
}
__device__ __forceinline__ float2 upk2(ull v) {
    float2 r; asm("mov.b64 {%0,%1},%2;" : "=f"(r.x), "=f"(r.y) : "l"(v)); return r;
}
__device__ __forceinline__ ull fma2(ull a, ull b, ull c) {
    ull r; asm("fma.rn.f32x2 %0,%1,%2,%3;" : "=l"(r) : "l"(a), "l"(b), "l"(c)); return r;
}
__device__ __forceinline__ ull mul2(ull a, ull b) {
    ull r; asm("mul.rn.f32x2 %0,%1,%2;" : "=l"(r) : "l"(a), "l"(b)); return r;
}
__device__ __forceinline__ float hadd2(ull v) { float2 f = upk2(v); return f.x + f.y; }
__device__ __forceinline__ float d4(float4 a, float4 b) {
    return fmaf(a.x, b.x, fmaf(a.y, b.y, fmaf(a.z, b.z, a.w * b.w)));
}
// collective: all 32 lanes must execute (full-mask shfl)
__device__ __forceinline__ void dots2(const ull* u, const ull* v, float& dd, float& apq) {
    ull U = mul2(u[0], u[0]), V = mul2(v[0], v[0]), P = mul2(u[0], v[0]);
#pragma unroll
    for (int i = 1; i < 4; i++) {
        U = fma2(u[i], u[i], U); V = fma2(v[i], v[i], V); P = fma2(u[i], v[i], P);
    }
    float d = hadd2(V) - hadd2(U);
    float p = hadd2(P);
#pragma unroll
    for (int k = 1; k < 8; k <<= 1) {
        d += __shfl_xor_sync(FULLM, d, k);
        p += __shfl_xor_sync(FULLM, p, k);
    }
    dd = d; apq = p;
}
__device__ __forceinline__ void rot_params2(float dd, float apq, float& c, float& s) {
    if (fabsf(apq) > 1e-34f) {
        float tau = __fdividef(dd, 2.f * apq);
        float tt  = copysignf(1.f, tau) / (fabsf(tau) + sqrtf(1.f + tau * tau));
        c = rsqrtf(1.f + tt * tt);
        s = tt * c;
    } else { c = 1.f; s = 0.f; }
}
__device__ __forceinline__ void get_pair(int r, int k, int& p, int& q) {
    int a = (k == 0) ? 0 : 1 + (k - 1 + r) % 63;
    int b = 1 + (62 - k + r) % 63;
    p = a < b ? a : b;
    q = a < b ? b : a;
}

// ---- single-matrix helpers ----
__device__ __forceinline__ void load_g2s(const float* __restrict__ g, float* S) {
    for (int idx = threadIdx.x; idx < NN; idx += TPB)
        S[(idx >> 6) * LD + (idx & 63)] = g[idx];
}
__device__ __forceinline__ void store_s2g(const float* S, float* __restrict__ g) {
    for (int idx = threadIdx.x; idx < NN; idx += TPB)
        g[idx] = S[(idx >> 6) * LD + (idx & 63)];
}
__device__ __forceinline__ void sym_s(float* A) {
    for (int idx = threadIdx.x; idx < NN; idx += TPB) {
        int i = idx >> 6, j = idx & 63;
        if (i < j) {
            float v = 0.5f * (A[i * LD + j] + A[j * LD + i]);
            A[i * LD + j] = v; A[j * LD + i] = v;
        }
    }
}
__device__ __forceinline__ void smm(const float* A, const float* B, float* C) {
    int j = threadIdx.x & 63, ib = (threadIdx.x >> 6) << 4;
    float acc[16];
#pragma unroll
    for (int i = 0; i < 16; i++) acc[i] = 0.f;
    for (int k = 0; k < 64; k++) {
        float bv = B[k * LD + j];
#pragma unroll
        for (int i = 0; i < 16; i++) acc[i] = fmaf(A[(ib + i) * LD + k], bv, acc[i]);
    }
#pragma unroll
    for (int i = 0; i < 16; i++) C[(ib + i) * LD + j] = acc[i];
}
__device__ __forceinline__ void smm_bt(const float* A, const float* B, float* C) {
    int j = threadIdx.x & 63, ib = (threadIdx.x >> 6) << 4;
    float acc[16];
#pragma unroll
    for (int i = 0; i < 16; i++) acc[i] = 0.f;
    for (int k = 0; k < 64; k++) {
        float bv = B[j * LD + k];
#pragma unroll
        for (int i = 0; i < 16; i++) acc[i] = fmaf(A[(ib + i) * LD + k], bv, acc[i]);
    }
#pragma unroll
    for (int i = 0; i < 16; i++) C[(ib + i) * LD + j] = acc[i];
}
__device__ __forceinline__ void smm_glob(const float* A, const float* B, float* __restrict__ g) {
    int j = threadIdx.x & 63, ib = (threadIdx.x >> 6) << 4;
    float acc[16];
#pragma unroll
    for (int i = 0; i < 16; i++) acc[i] = 0.f;
    for (int k = 0; k < 64; k++) {
        float bv = B[k * LD + j];
#pragma unroll
        for (int i = 0; i < 16; i++) acc[i] = fmaf(A[(ib + i) * LD + k], bv, acc[i]);
    }
#pragma unroll
    for (int i = 0; i < 16; i++) g[(ib + i) * 64 + j] = acc[i];
}
__device__ __forceinline__ void scalecols(const float* V, const float* w, float* O) {
    for (int idx = threadIdx.x; idx < NN; idx += TPB) {
        int i = idx >> 6, k = idx & 63;
        O[i * LD + k] = V[i * LD + k] * w[k];
    }
}

__device__ void jacobi2s(float* A, float* V, int nsweeps) {
    int t = threadIdx.x;
    __shared__ float cs[32], sn[32];
    __shared__ uchar2 tab2[63 * 32];
    for (int idx = t; idx < 63 * 32; idx += TPB) {
        int r = idx >> 5, k = idx & 31, p, q;
        get_pair(r, k, p, q);
        tab2[idx] = make_uchar2((unsigned char)p, (unsigned char)q);
    }
    for (int idx = t; idx < NN; idx += TPB) {
        int i = idx >> 6, j = idx & 63;
        V[i * LD + j] = (i == j) ? 1.f : 0.f;
    }
    __syncthreads();
    for (int sw = 0; sw < nsweeps; ++sw)
        for (int r = 0; r < 63; ++r) {
            const uchar2* trow = tab2 + (r << 5);
            if (t < 32) {
                uchar2 pq = trow[t];
                int pl = pq.x * LD, ql = pq.y * LD;
                float app = A[pl + pq.x], aqq = A[ql + pq.y], apq = A[pl + pq.y];
                float c, s;
                if (fabsf(apq) < 1e-30f) { c = 1.f; s = 0.f; }
                else {
                    float tau = (aqq - app) / (2.f * apq);
                    float tt  = copysignf(1.f, tau) / (fabsf(tau) + sqrtf(1.f + tau * tau));
                    c = rsqrtf(1.f + tt * tt); s = tt * c;
                }
                cs[t] = c; sn[t] = s;
            }
            __syncthreads();
#pragma unroll
            for (int m = 0; m < 2048 / TPB; m++) {
                int w = t + m * TPB, k = w >> 6, j = w & 63;
                uchar2 pq = trow[k];
                int pl = pq.x * LD + j, ql = pq.y * LD + j;
                float c = cs[k], s = sn[k];
                float ap = A[pl], aq = A[ql];
                A[pl] = c * ap - s * aq;
                A[ql] = fmaf(s, ap, c * aq);
            }
            __syncthreads();
#pragma unroll
            for (int m = 0; m < 2048 / TPB; m++) {
                int w = t + m * TPB, k = w >> 6, i = w & 63;
                uchar2 pq = trow[k];
                int il = i * LD, pl = il + pq.x, ql = il + pq.y;
                float c = cs[k], s = sn[k];
                float ap = A[pl], aq = A[ql];
                A[pl] = c * ap - s * aq;
                A[ql] = fmaf(s, ap, c * aq);
                float vp = V[pl], vq = V[ql];
                V[pl] = c * vp - s * vq;
                V[ql] = fmaf(s, vp, c * vq);
            }
            __syncthreads();
        }
}

// ---- batch GEMMs ----
__device__ __forceinline__ void gemm_rr(const float* A, const float* B, float* C) {
    int j = threadIdx.x & 63, ib = (threadIdx.x >> 6) << 4;
    ull acc[16];
#pragma unroll
    for (int i = 0; i < 16; i++) acc[i] = 0ull;
    for (int k = 0; k < 64; k += 2) {
        ull b2 = pk2(B[k * BLD + j], B[(k + 1) * BLD + j]);
#pragma unroll
        for (int i = 0; i < 16; i++)
            acc[i] = fma2(*(const ull*)(A + (ib + i) * BLD + k), b2, acc[i]);
    }
#pragma unroll
    for (int i = 0; i < 16; i++) { float2 f = upk2(acc[i]); C[(ib + i) * BLD + j] = f.x + f.y; }
}
__device__ __forceinline__ void gemm_r2c(const float* A, const float* B, float* C) {
    int j = threadIdx.x & 63, ib = (threadIdx.x >> 6) << 4;
    ull acc[16];
#pragma unroll
    for (int i = 0; i < 16; i++) acc[i] = 0ull;
    for (int k = 0; k < 64; k += 2) {
        ull b2 = pk2(B[k * BLD + j], B[(k + 1) * BLD + j]);
#pragma unroll
        for (int i = 0; i < 16; i++)
            acc[i] = fma2(*(const ull*)(A + (ib + i) * BLD + k), b2, acc[i]);
    }
    float r[16];
#pragma unroll
    for (int i = 0; i < 16; i++) { float2 f = upk2(acc[i]); r[i] = f.x + f.y; }
    float4* dst = (float4*)(C + j * CST + ib);
    dst[0] = make_float4(r[0], r[1], r[2], r[3]);
    dst[1] = make_float4(r[4], r[5], r[6], r[7]);
    dst[2] = make_float4(r[8], r[9], r[10], r[11]);
    dst[3] = make_float4(r[12], r[13], r[14], r[15]);
}

// fused logm epilogue: g_T += scale * B diag(g) B^T
__device__ __forceinline__ void logm_fused_atomic(const float* B, float* sg, float scale) {
    int t = threadIdx.x;
    {
        int col = t >> 2, qc = t & 3;
        const float4* bc = (const float4*)(B + col * CST);
        float4 v0 = bc[qc * 4 + 0], v1 = bc[qc * 4 + 1];
        float4 v2 = bc[qc * 4 + 2], v3 = bc[qc * 4 + 3];
        float pn = d4(v0, v0) + d4(v1, v1) + d4(v2, v2) + d4(v3, v3);
        pn += __shfl_xor_sync(FULLM, pn, 1);
        pn += __shfl_xor_sync(FULLM, pn, 2);
        float n2 = fmaxf(pn, 1e-24f);
        if (qc == 0) sg[col] = 0.5f * logf(n2) / n2;
    }
    __syncthreads();
    int j = t & 63, ib = (t >> 6) << 4;
    ull acc[8];
#pragma unroll
    for (int p = 0; p < 8; p++) acc[p] = 0ull;
    for (int k = 0; k < 64; k++) {
        float bj = B[k * CST + j] * sg[k];
        ull bj2 = pk2(bj, bj);
        const ulonglong2* wr = (const ulonglong2*)(B + k * CST + ib);
        ulonglong2 w0 = wr[0], w1 = wr[1];
        acc[0] = fma2(w0.x, bj2, acc[0]);
        acc[1] = fma2(w0.y, bj2, acc[1]);
        acc[2] = fma2(w1.x, bj2, acc[2]);
        acc[3] = fma2(w1.y, bj2, acc[3]);
        ulonglong2 w2 = wr[2], w3 = wr[3];
        acc[4] = fma2(w2.x, bj2, acc[4]);
        acc[5] = fma2(w2.y, bj2, acc[5]);
        acc[6] = fma2(w3.x, bj2, acc[6]);
        acc[7] = fma2(w3.y, bj2, acc[7]);
    }
#pragma unroll
    for (int p = 0; p < 8; p++) {
        float2 f = upk2(acc[p]);
        atomicAdd(&g_T[(ib + 2 * p) * 64 + j],     f.x * scale);
        atomicAdd(&g_T[(ib + 2 * p + 1) * 64 + j], f.y * scale);
    }
}

// ---- kernels ----
__global__ void k_zero0() {
    int i = blockIdx.x * blockDim.x + threadIdx.x;
    if (i < NN) g_M[i] = 0.f;
}
__global__ void k_mean_acc(const float* __restrict__ data, int per_chunk, float inv_nb) {
    int e = blockIdx.x * blockDim.x + threadIdx.x;
    const float* p = data + (size_t)(blockIdx.y) * per_chunk * NN + e;
    float sum = 0.f;
#pragma unroll 8
    for (int i = 0; i < per_chunk; i++) sum += p[(size_t)i * NN];
    atomicAdd(&g_M[e], sum * inv_nb);
}

// eig of M -> Ms/Mi; also zeroes g_T (consumed by prior k_update_M)
__device__ __forceinline__ void eig_M_body(float* sm) {
    float* A = sm; float* V = sm + BUF; float* T1 = sm + 2 * BUF; float* T2 = sm + 3 * BUF;
    __shared__ float w1[64], w2[64];
    int t = threadIdx.x;
    for (int idx = t; idx < NN; idx += TPB) g_T[idx] = 0.f;
    load_g2s(g_M, A); __syncthreads();
    sym_s(A); __syncthreads();
    jacobi2s(A, V, NSWEEP_S);
    if (t < 64) {
        float w = fmaxf(A[t * LD + t], 1e-12f);
        w1[t] = sqrtf(w); w2[t] = rsqrtf(w);
    }
    __syncthreads();
    scalecols(V, w1, T1); __syncthreads();
    smm_bt(T1, V, T2);    __syncthreads();
    store_s2g(T2, g_Ms);  __syncthreads();
    scalecols(V, w2, T1); __syncthreads();
    smm_bt(T1, V, T2);    __syncthreads();
    store_s2g(T2, g_Mi);
}
__global__ void __launch_bounds__(TPB) k_eig_M() {
    extern __shared__ float sm[];
    eig_M_body(sm);
}
// final eig kernel: block 0 = eig of M; block 1 = bias eigh -> S (concurrent)
__global__ void __launch_bounds__(TPB) k_eig_final(const float* __restrict__ bias) {
    extern __shared__ float sm[];
    if (blockIdx.x == 0) {
        eig_M_body(sm);
    } else {
        float* A = sm; float* V = sm + BUF; float* T1 = sm + 2 * BUF; float* T2 = sm + 3 * BUF;
        __shared__ float ew[64];
        int t = threadIdx.x;
        for (int idx = t; idx < NN; idx += TPB) {
            int i = idx >> 6, j = idx & 63;
            A[i * LD + j] = 0.5f * (bias[i * 64 + j] + bias[j * 64 + i]);
        }
        __syncthreads();
        jacobi2s(A, V, NSWEEP_S);
        if (t < 64) ew[t] = expf(0.5f * A[t * LD + t]);
        __syncthreads();
        scalecols(V, ew, T1); __syncthreads();
        smm_bt(T1, V, T2);    __syncthreads();
        store_s2g(T2, g_S);
    }
}
// W = S * Mi (1 CTA)
__global__ void __launch_bounds__(TPB) k_mkW() {
    extern __shared__ float sm[];
    float* A = sm; float* B = sm + BUF;
    load_g2s(g_S, A);
    load_g2s(g_Mi, B);
    __syncthreads();
    smm_glob(A, B, g_W);
}

// batch step
__global__ void __launch_bounds__(TPB, 4) k_batch_oe(const float* __restrict__ data,
                                                     float inv_nb, int nsweep) {
    extern __shared__ float sm[];
    float* s0 = sm;             // Mi(row) -> xL overlay
    float* s1 = sm + BUFB;      // D(row) -> C(col) -> B(col)
    float* s2 = sm + 2 * BUFB;  // temp(row) -> xR overlay
    __shared__ float2 prm[2][32];
    __shared__ float sg[64];
    int t = threadIdx.x;
    size_t b = blockIdx.x;

    for (int idx = t; idx < NN; idx += TPB)
        s0[(idx >> 6) * BLD + (idx & 63)] = g_Mi[idx];
    const float* D = data + b * NN;
    for (int idx = t; idx < NN; idx += TPB)
        s1[(idx >> 6) * BLD + (idx & 63)] = D[idx];
    __syncthreads();
    gemm_rr(s0, s1, s2);
    __syncthreads();
    gemm_r2c(s2, s0, s1);
    __syncthreads();
    for (int idx = t; idx < NN; idx += TPB) {
        int i = idx >> 6, j = idx & 63;
        if (i < j) {
            float v = 0.5f * (s1[i * CST + j] + s1[j * CST + i]);
            s1[i * CST + j] = v; s1[j * CST + i] = v;
        }
    }
    __syncthreads();

    int lane = t & 31, warp = t >> 5, grp = lane >> 3, sub = lane & 7;
    int G = warp * 4 + grp;
    ull cL[4], cR[4];
    {
        const ulonglong2* pc = (const ulonglong2*)(s1 + (2 * G) * CST);
        ulonglong2 q0 = pc[2 * sub], q1 = pc[2 * sub + 1];
        cL[0] = q0.x; cL[1] = q0.y; cL[2] = q1.x; cL[3] = q1.y;
        const ulonglong2* pd = (const ulonglong2*)(s1 + (2 * G + 1) * CST);
        q0 = pd[2 * sub]; q1 = pd[2 * sub + 1];
        cR[0] = q0.x; cR[1] = q0.y; cR[2] = q1.x; cR[3] = q1.y;
    }
    __syncthreads();

    const bool hasR = (G < 31);
    const bool hasL = (G > 0);
    int pb = 0;
    for (int sw = 0; sw < nsweep; ++sw)
        for (int rr = 0; rr < 32; ++rr) {
            {   // EVEN round
                float dd, apq;
                dots2(cL, cR, dd, apq);
                float c, s;
                rot_params2(dd, apq, c, s);
                ull c2 = pk2(c, c), s2p = pk2(s, s), ns2 = pk2(-s, -s);
#pragma unroll
                for (int i = 0; i < 4; i++) {
                    ull u = cL[i], v = cR[i];
                    cL[i] = fma2(s2p, u, mul2(c2, v));
                    cR[i] = fma2(ns2, v, mul2(c2, u));
                }
            }
            {   // ODD round
                float4* Lb = (float4*)(s0 + ((pb << 5) + G) * 64);
                float4* Rb = (float4*)(s2 + ((pb << 5) + G) * 64);
                Lb[sub]     = *(float4*)&cL[0];
                Lb[sub + 8] = *(float4*)&cL[2];
                Rb[sub]     = *(float4*)&cR[0];
                Rb[sub + 8] = *(float4*)&cR[2];
                __syncthreads();
                ull vR[4] = {0, 0, 0, 0}, uL[4] = {0, 0, 0, 0};
                if (hasR) {
                    const float4* p = (const float4*)(s0 + ((pb << 5) + G + 1) * 64);
                    *(float4*)&vR[0] = p[sub];
                    *(float4*)&vR[2] = p[sub + 8];
                }
                if (hasL) {
                    const float4* p = (const float4*)(s2 + ((pb << 5) + G - 1) * 64);
                    *(float4*)&uL[0] = p[sub];
                    *(float4*)&uL[2] = p[sub + 8];
                }
                float dd, apq;
                dots2(cR, vR, dd, apq);
                float c, s;
                rot_params2(dd, apq, c, s);
                if (sub == 0) prm[pb][G] = make_float2(c, s);
                __syncthreads();
                if (hasR) {
                    ull c2 = pk2(c, c), s2p = pk2(s, s);
#pragma unroll
                    for (int i = 0; i < 4; i++)
                        cR[i] = fma2(s2p, cR[i], mul2(c2, vR[i]));
                }
                if (hasL) {
                    float2 ps = prm[pb][G - 1];
                    ull cl2 = pk2(ps.x, ps.x), nsl2 = pk2(-ps.y, -ps.y);
#pragma unroll
                    for (int i = 0; i < 4; i++)
                        cL[i] = fma2(nsl2, cL[i], mul2(cl2, uL[i]));
                }
                pb ^= 1;
            }
        }

    {
        ulonglong2* pc = (ulonglong2*)(s1 + (2 * G) * CST);
        pc[2 * sub]     = make_ulonglong2(cL[0], cL[1]);
        pc[2 * sub + 1] = make_ulonglong2(cL[2], cL[3]);
        ulonglong2* pd = (ulonglong2*)(s1 + (2 * G + 1) * CST);
        pd[2 * sub]     = make_ulonglong2(cR[0], cR[1]);
        pd[2 * sub + 1] = make_ulonglong2(cR[2], cR[3]);
    }
    __syncthreads();
    logm_fused_atomic(s1, sg, inv_nb);
}

__global__ void __launch_bounds__(TPB) k_update_M() {
    extern __shared__ float sm[];
    float* A = sm; float* V = sm + BUF; float* T1 = sm + 2 * BUF; float* T2 = sm + 3 * BUF;
    __shared__ float ew[64];
    load_g2s(g_T, A); __syncthreads();
    sym_s(A); __syncthreads();
    jacobi2s(A, V, NSWEEP_S);
    int t = threadIdx.x;
    if (t < 64) ew[t] = expf(A[t * LD + t]);
    __syncthreads();
    scalecols(V, ew, T1); __syncthreads();
    smm_bt(T1, V, T2);    __syncthreads();
    load_g2s(g_Ms, A);    __syncthreads();
    smm(A, T2, T1);       __syncthreads();
    smm_glob(T1, A, g_M);
}
__global__ void __launch_bounds__(TPB, 4) k_final(const float* __restrict__ data,
                                                  float* __restrict__ out) {
    extern __shared__ float sm[];
    float* sW = sm; float* sD = sm + BUFB; float* sT = sm + 2 * BUFB;
    size_t b = blockIdx.x;
    int t = threadIdx.x;
    for (int idx = t; idx < NN; idx += TPB)
        sW[(idx >> 6) * BLD + (idx & 63)] = g_W[idx];
    const float* D = data + b * NN;
    for (int idx = t; idx < NN; idx += TPB)
        sD[(idx >> 6) * BLD + (idx & 63)] = D[idx];
    __syncthreads();
    gemm_rr(sW, sD, sT);
    __syncthreads();
    int j = t & 63, ib = (t >> 6) << 4;
    ull acc[16];
#pragma unroll
    for (int i = 0; i < 16; i++) acc[i] = 0ull;
    for (int k = 0; k < 64; k += 2) {
        ull b2 = *(const ull*)(sW + j * BLD + k);
#pragma unroll
        for (int i = 0; i < 16; i++)
            acc[i] = fma2(*(const ull*)(sT + (ib + i) * BLD + k), b2, acc[i]);
    }
    float* o = out + b * NN;
#pragma unroll
    for (int i = 0; i < 16; i++) { float2 f = upk2(acc[i]); o[(ib + i) * 64 + j] = f.x + f.y; }
}

// ---------------------------------------------------------------------------
extern "C" void kernel_launch(void* const* d_in, const int* in_sizes, int n_in,
                              void* d_out, int out_size) {
    const float* data;
    const float* bias;
    int nb;
    if (in_sizes[0] >= in_sizes[1]) {
        data = (const float*)d_in[0]; bias = (const float*)d_in[1];
        nb = in_sizes[0] / NN;
    } else {
        data = (const float*)d_in[1]; bias = (const float*)d_in[0];
        nb = in_sizes[1] / NN;
    }
    float* out = (float*)d_out;
    float inv_nb = 1.0f / (float)nb;

    size_t smemS = 4 * BUF  * sizeof(float);
    size_t smemB = 3 * BUFB * sizeof(float);
    cudaFuncSetAttribute(k_eig_M,     cudaFuncAttributeMaxDynamicSharedMemorySize, (int)smemS);
    cudaFuncSetAttribute(k_eig_final, cudaFuncAttributeMaxDynamicSharedMemorySize, (int)smemS);
    cudaFuncSetAttribute(k_mkW,       cudaFuncAttributeMaxDynamicSharedMemorySize, (int)smemS);
    cudaFuncSetAttribute(k_batch_oe,  cudaFuncAttributeMaxDynamicSharedMemorySize, (int)smemB);
    cudaFuncSetAttribute(k_update_M,  cudaFuncAttributeMaxDynamicSharedMemorySize, (int)smemS);
    cudaFuncSetAttribute(k_final,     cudaFuncAttributeMaxDynamicSharedMemorySize, (int)smemB);

    k_zero0<<<16, 256>>>();
    {
        int nchunk = 64;
        while (nchunk > 1 && (nb % nchunk) != 0) nchunk >>= 1;
        int per_chunk = nb / nchunk;
        dim3 g(NN / 256, nchunk);
        k_mean_acc<<<g, 256>>>(data, per_chunk, inv_nb);
    }

    // Karcher iterations: sweep schedule 5/5/7
    const int sweeps[3] = {5, 5, 7};
    for (int it = 0; it < 3; ++it) {
        k_eig_M<<<1, TPB, smemS>>>();   // also zeroes g_T
        k_batch_oe<<<nb, TPB, smemB>>>(data, inv_nb, sweeps[it]);
        k_update_M<<<1, TPB, smemS>>>();
    }

    k_eig_final<<<2, TPB, smemS>>>(bias);   // block0: Mi; block1: S (concurrent)
    k_mkW<<<1, TPB, smemS>>>();             // W = S * Mi
    k_final<<<nb, TPB, smemB>>>(data, out);
}